// round 14
// baseline (speedup 1.0000x reference)
#include <cuda_runtime.h>
#include <cuda_fp16.h>

typedef unsigned long long ull;
typedef unsigned int uint;

#define NTHREADS 512
#define RAYS 8
#define NBLOCKS 4096
#define B_TOTAL 32768
#define S_A 68      // fp32 tile stride (floats)
#define S_H 72      // half tile stride (halves); word stride 36

// smem offsets (floats); half tile = 64*72 halves = 2304 floats
#define OFF_Q    0              // fp32 q tile; ALIASED as ao tile (disjoint lifetimes)
#define OFF_K    4352
#define OFF_V    8704
#define OFF_ACTH 13056
#define OFF_ACTL 15360
#define OFF_XH   17664
#define OFF_XL   19968
#define OFF_WB   22272          // 14 half tiles: s0(3 pairs), w3 pair, s1(3 pairs)
#define TILE_F   2304
#define OFF_P    (OFF_WB + 14 * TILE_F)   // 54528
#define SMEM_FLOATS (OFF_P + 512)         // 55040 floats = 220160 B
#define SMEM_BYTES (SMEM_FLOATS * 4)

struct Params {
  const float *query, *latent, *W1, *b1;
  const float *Wq, *bq, *Wk, *bk, *Wv, *bv, *Wo, *bo;
  const float *fW1, *fb1, *fW2, *fb2, *g1, *be1, *g2, *be2;
  const float *cWq, *cbq, *cWk, *cbk, *cWv, *cbv, *cWo, *cbo;
  const float *Wc, *bc, *Ws, *bs;
  float *o_color, *o_sigma, *o_out, *o_attn;
};

// ---------------- helpers ----------------
__device__ __forceinline__ ull ffma2(ull a, ull b, ull c) {
  ull d;
  asm("fma.rn.f32x2 %0, %1, %2, %3;" : "=l"(d) : "l"(a), "l"(b), "l"(c));
  return d;
}
__device__ __forceinline__ ull pack2(float lo, float hi) {
  ull d;
  asm("mov.b64 %0, {%1, %2};" : "=l"(d) : "f"(lo), "f"(hi));
  return d;
}
__device__ __forceinline__ float2 unpack2(ull v) {
  float lo, hi;
  asm("mov.b64 {%0, %1}, %2;" : "=f"(lo), "=f"(hi) : "l"(v));
  return make_float2(lo, hi);
}
__device__ __forceinline__ uint hpackr(float a, float b, float& ra, float& rb) {
  __half ha = __float2half_rn(a), hb = __float2half_rn(b);
  ra = a - __half2float(ha);
  rb = b - __half2float(hb);
  __half2 p = __halves2half2(ha, hb);
  return *(uint*)&p;
}
__device__ __forceinline__ uint hpack(float a, float b) {
  __half2 p = __halves2half2(__float2half_rn(a), __float2half_rn(b));
  return *(uint*)&p;
}
__device__ __forceinline__ float2 h2f(uint u) {
  return __half22float2(*(__half2*)&u);
}
__device__ __forceinline__ void hsplit1(float x, __half& h, __half& l) {
  h = __float2half_rn(x);
  l = __float2half_rn(x - __half2float(h));
}

__device__ __forceinline__ void mma16(float c[4], uint a0, uint a1, uint a2, uint a3,
                                      uint b0, uint b1) {
  asm("mma.sync.aligned.m16n8k16.row.col.f32.f16.f16.f32 "
      "{%0,%1,%2,%3},{%4,%5,%6,%7},{%8,%9},{%0,%1,%2,%3};"
      : "+f"(c[0]), "+f"(c[1]), "+f"(c[2]), "+f"(c[3])
      : "r"(a0), "r"(a1), "r"(a2), "r"(a3), "r"(b0), "r"(b1));
}

struct AF { uint h[4], l[4]; };
__device__ __forceinline__ AF load_a(const uint* __restrict__ Ah,
                                     const uint* __restrict__ Al,
                                     int lane, int mt, int kk) {
  const int grp = lane >> 2, kq = lane & 3;
  const int base = (mt * 16 + grp) * 36 + kk * 8 + kq;
  AF f;
  f.h[0] = Ah[base];
  f.h[1] = Ah[base + 8 * 36];
  f.h[2] = Ah[base + 4];
  f.h[3] = Ah[base + 8 * 36 + 4];
  f.l[0] = Al[base];
  f.l[1] = Al[base + 8 * 36];
  f.l[2] = Al[base + 4];
  f.l[3] = Al[base + 8 * 36 + 4];
  return f;
}
__device__ __forceinline__ void mma3h(float c[4], const AF& a,
                                      uint wh0, uint wh1, uint wl0, uint wl1) {
  mma16(c, a.h[0], a.h[1], a.h[2], a.h[3], wh0, wh1);
  mma16(c, a.l[0], a.l[1], a.l[2], a.l[3], wh0, wh1);
  mma16(c, a.h[0], a.h[1], a.h[2], a.h[3], wl0, wl1);
}

// 16-warp m16n16 single gemm (stage0, FF1, FF2, cross gemm2)
__device__ __forceinline__ void gemm_acc(const uint* Ah, const uint* Al,
                                         const uint* Wh, const uint* Wl,
                                         int lane, int mt, int nq, float c[2][4]) {
  const int grp = lane >> 2, kq = lane & 3;
  #pragma unroll
  for (int kk = 0; kk < 4; kk++) {
    AF a = load_a(Ah, Al, lane, mt, kk);
    const int off = (nq * 16 + grp) * 36 + kk * 8 + kq;
    #pragma unroll
    for (int t = 0; t < 2; t++) {
      const int o = off + t * 8 * 36;
      mma3h(c[t], a, Wh[o], Wh[o + 4], Wl[o], Wl[o + 4]);
    }
  }
}
__device__ __forceinline__ void gemm2_acc(const uint* Ah, const uint* Al,
                                          const uint* W0h, const uint* W0l,
                                          const uint* W1h, const uint* W1l,
                                          int lane, int mt, int nq,
                                          float c0[2][4], float c1[2][4]) {
  const int grp = lane >> 2, kq = lane & 3;
  #pragma unroll
  for (int kk = 0; kk < 4; kk++) {
    AF a = load_a(Ah, Al, lane, mt, kk);
    const int off = (nq * 16 + grp) * 36 + kk * 8 + kq;
    #pragma unroll
    for (int t = 0; t < 2; t++) {
      const int o = off + t * 8 * 36;
      mma3h(c0[t], a, W0h[o], W0h[o + 4], W0l[o], W0l[o + 4]);
      mma3h(c1[t], a, W1h[o], W1h[o + 4], W1l[o], W1l[o + 4]);
    }
  }
}

// 8-warp m32n16 fused QKV: warps 0-7 = (mh in 0..1) x (nq in 0..3).
// W read redundancy 2 (vs 4), A unchanged. W frags hoisted across mt2.
__device__ __forceinline__ void gemm3_8(const uint* Ah, const uint* Al,
                                        const uint* W0h, const uint* W0l,
                                        const uint* W1h, const uint* W1l,
                                        const uint* W2h, const uint* W2l,
                                        int lane, int mh, int nq,
                                        float cq[2][2][4], float ck[2][2][4],
                                        float cv[2][2][4]) {
  const int grp = lane >> 2, kq = lane & 3;
  #pragma unroll
  for (int kk = 0; kk < 4; kk++) {
    const int off = (nq * 16 + grp) * 36 + kk * 8 + kq;
    uint wh[3][2][2], wl[3][2][2];
    #pragma unroll
    for (int t = 0; t < 2; t++) {
      const int o = off + t * 8 * 36;
      wh[0][t][0] = W0h[o]; wh[0][t][1] = W0h[o + 4];
      wl[0][t][0] = W0l[o]; wl[0][t][1] = W0l[o + 4];
      wh[1][t][0] = W1h[o]; wh[1][t][1] = W1h[o + 4];
      wl[1][t][0] = W1l[o]; wl[1][t][1] = W1l[o + 4];
      wh[2][t][0] = W2h[o]; wh[2][t][1] = W2h[o + 4];
      wl[2][t][0] = W2l[o]; wl[2][t][1] = W2l[o + 4];
    }
    #pragma unroll
    for (int mt2 = 0; mt2 < 2; mt2++) {
      AF a = load_a(Ah, Al, lane, mh * 2 + mt2, kk);
      #pragma unroll
      for (int t = 0; t < 2; t++) {
        mma3h(cq[mt2][t], a, wh[0][t][0], wh[0][t][1], wl[0][t][0], wl[0][t][1]);
        mma3h(ck[mt2][t], a, wh[1][t][0], wh[1][t][1], wl[1][t][0], wl[1][t][1]);
        mma3h(cv[mt2][t], a, wh[2][t][0], wh[2][t][1], wl[2][t][0], wl[2][t][1]);
      }
    }
  }
}

// 8-warp m32n16 single gemm (out-proj)
__device__ __forceinline__ void gemm_8(const uint* Ah, const uint* Al,
                                       const uint* Wh, const uint* Wl,
                                       int lane, int mh, int nq, float c[2][2][4]) {
  const int grp = lane >> 2, kq = lane & 3;
  #pragma unroll
  for (int kk = 0; kk < 4; kk++) {
    const int off = (nq * 16 + grp) * 36 + kk * 8 + kq;
    uint wh[2][2], wl[2][2];
    #pragma unroll
    for (int t = 0; t < 2; t++) {
      const int o = off + t * 8 * 36;
      wh[t][0] = Wh[o]; wh[t][1] = Wh[o + 4];
      wl[t][0] = Wl[o]; wl[t][1] = Wl[o + 4];
    }
    #pragma unroll
    for (int mt2 = 0; mt2 < 2; mt2++) {
      AF a = load_a(Ah, Al, lane, mh * 2 + mt2, kk);
      #pragma unroll
      for (int t = 0; t < 2; t++)
        mma3h(c[mt2][t], a, wh[t][0], wh[t][1], wl[t][0], wl[t][1]);
    }
  }
}

__device__ __forceinline__ void store_c(float* D, int lane, int mt, int nq,
                                        const float c[2][4], const float* bias,
                                        int do_relu, const uint* rh, const uint* rl) {
  const int grp = lane >> 2, kq = lane & 3;
  const int r = mt * 16 + grp;
  #pragma unroll
  for (int t = 0; t < 2; t++) {
    int col = nq * 16 + t * 8 + 2 * kq;
    float b0 = __ldg(bias + col), b1 = __ldg(bias + col + 1);
    float v0 = c[t][0] + b0, v1 = c[t][1] + b1;
    float v2 = c[t][2] + b0, v3 = c[t][3] + b1;
    if (rh) {
      int w0 = r * 36 + (col >> 1), w1 = (r + 8) * 36 + (col >> 1);
      float2 fh0 = h2f(rh[w0]), fl0 = h2f(rl[w0]);
      float2 fh1 = h2f(rh[w1]), fl1 = h2f(rl[w1]);
      v0 += fh0.x + fl0.x; v1 += fh0.y + fl0.y;
      v2 += fh1.x + fl1.x; v3 += fh1.y + fl1.y;
    }
    if (do_relu) {
      v0 = fmaxf(v0, 0.f); v1 = fmaxf(v1, 0.f);
      v2 = fmaxf(v2, 0.f); v3 = fmaxf(v3, 0.f);
    }
    *(float2*)(D + r * S_A + col) = make_float2(v0, v1);
    *(float2*)(D + (r + 8) * S_A + col) = make_float2(v2, v3);
  }
}

__device__ __forceinline__ void store_c_h(uint* Dh, uint* Dl, int lane, int mt, int nq,
                                          const float c[2][4], const float* bias,
                                          int do_relu) {
  const int grp = lane >> 2, kq = lane & 3;
  const int r = mt * 16 + grp;
  #pragma unroll
  for (int t = 0; t < 2; t++) {
    int col = nq * 16 + t * 8 + 2 * kq;
    float b0 = __ldg(bias + col), b1 = __ldg(bias + col + 1);
    float v0 = c[t][0] + b0, v1 = c[t][1] + b1;
    float v2 = c[t][2] + b0, v3 = c[t][3] + b1;
    if (do_relu) {
      v0 = fmaxf(v0, 0.f); v1 = fmaxf(v1, 0.f);
      v2 = fmaxf(v2, 0.f); v3 = fmaxf(v3, 0.f);
    }
    float ra, rb;
    uint h01 = hpackr(v0, v1, ra, rb);
    uint l01 = hpack(ra, rb);
    Dh[r * 36 + (col >> 1)] = h01;
    Dl[r * 36 + (col >> 1)] = l01;
    uint h23 = hpackr(v2, v3, ra, rb);
    uint l23 = hpack(ra, rb);
    Dh[(r + 8) * 36 + (col >> 1)] = h23;
    Dl[(r + 8) * 36 + (col >> 1)] = l23;
  }
}

// staging: split 64x64 fp32 weight [k][n] -> transposed [n][k] half hi/lo tiles
// TID256 variant runs on warps 8-15 (256 threads), FULL variant on all 512.
__device__ __forceinline__ void stage_body(const float* __restrict__ src, int stride,
                                           __half* __restrict__ dh,
                                           __half* __restrict__ dl, int i) {
  int n = i & 63, k4 = (i >> 6) << 2;
  float v0 = src[(k4 + 0) * stride + n];
  float v1 = src[(k4 + 1) * stride + n];
  float v2 = src[(k4 + 2) * stride + n];
  float v3 = src[(k4 + 3) * stride + n];
  float r0, r1, r2, r3;
  uint2 hw, lw;
  hw.x = hpackr(v0, v1, r0, r1);
  hw.y = hpackr(v2, v3, r2, r3);
  lw.x = hpack(r0, r1);
  lw.y = hpack(r2, r3);
  *(uint2*)(dh + n * S_H + k4) = hw;
  *(uint2*)(dl + n * S_H + k4) = lw;
}
__device__ __forceinline__ void stage_w_h(const float* src, int stride,
                                          __half* dh, __half* dl, int tid) {
  #pragma unroll
  for (int it = 0; it < 2; it++) stage_body(src, stride, dh, dl, tid + it * NTHREADS);
}
__device__ __forceinline__ void stage_w_h8(const float* src, int stride,
                                           __half* dh, __half* dl, int t8) {
  #pragma unroll
  for (int it = 0; it < 4; it++) stage_body(src, stride, dh, dl, t8 + it * 256);
}

__device__ __forceinline__ void ln4(const float* s1, const __half* s2h,
                                    const __half* s2l, const float* g,
                                    const float* be, int lane,
                                    __half* dh, __half* dl) {
  float gg0 = __ldg(g + lane), gg1 = __ldg(g + lane + 32);
  float bb0 = __ldg(be + lane), bb1 = __ldg(be + lane + 32);
  #pragma unroll
  for (int s = 0; s < 4; s++) {
    float x0 = s1[s * S_A + lane];
    float x1 = s1[s * S_A + lane + 32];
    if (s2h) {
      x0 += __half2float(s2h[s * S_H + lane]) + __half2float(s2l[s * S_H + lane]);
      x1 += __half2float(s2h[s * S_H + lane + 32]) + __half2float(s2l[s * S_H + lane + 32]);
    }
    float sum = x0 + x1;
    #pragma unroll
    for (int o = 16; o > 0; o >>= 1) sum += __shfl_xor_sync(0xffffffffu, sum, o);
    float mean = sum * 0.015625f;
    float d0 = x0 - mean, d1 = x1 - mean;
    float vs = d0 * d0 + d1 * d1;
    #pragma unroll
    for (int o = 16; o > 0; o >>= 1) vs += __shfl_xor_sync(0xffffffffu, vs, o);
    float rstd = rsqrtf(vs * 0.015625f + 1e-5f);
    float y0 = d0 * rstd * gg0 + bb0;
    float y1 = d1 * rstd * gg1 + bb1;
    __half h, l;
    hsplit1(y0, h, l);
    dh[s * S_H + lane] = h; dl[s * S_H + lane] = l;
    hsplit1(y1, h, l);
    dh[s * S_H + lane + 32] = h; dl[s * S_H + lane + 32] = l;
  }
}

#define STAGE_LAT(DH, DL, KC)                                                  \
  do {                                                                         \
    _Pragma("unroll")                                                          \
    for (int it_ = 0; it_ < 2; it_++) {                                        \
      int i_ = tid + it_ * NTHREADS;                                           \
      int row_ = i_ >> 4, j_ = (i_ & 15) * 4;                                  \
      float4 v_ = *(const float4*)(p.latent + (size_t)(bbase + (row_ >> 3)) * 4096 + \
                                   (row_ & 7) * 512 + (KC) * 64 + j_);         \
      float r0_, r1_, r2_, r3_;                                                \
      uint2 hw_, lw_;                                                          \
      hw_.x = hpackr(v_.x, v_.y, r0_, r1_);                                    \
      hw_.y = hpack(v_.z, v_.w);                                               \
      /* careful: need residuals for z,w too */                                \
      hw_.y = hpackr(v_.z, v_.w, r2_, r3_);                                    \
      lw_.x = hpack(r0_, r1_);                                                 \
      lw_.y = hpack(r2_, r3_);                                                 \
      *(uint2*)((DH) + row_ * S_H + j_) = hw_;                                 \
      *(uint2*)((DL) + row_ * S_H + j_) = lw_;                                 \
    }                                                                          \
  } while (0)

__global__ void __launch_bounds__(NTHREADS, 1) rt_kernel(Params p) {
  extern __shared__ float sm[];
  const int tid = threadIdx.x;
  const int warp = tid >> 5, lane = tid & 31;
  const int mt = warp & 3, nq = warp >> 2;          // 16-warp gemm roles
  const int mh = (warp >> 2) & 1, nq8 = warp & 3;   // 8-warp gemm roles (warps 0-7)
  const int t8 = tid & 255;                          // staging index for warps 8-15
  const int ray = warp & 7, half_ = warp >> 3, rb = half_ * 4;
  const int bbase = blockIdx.x * RAYS;
  const int b = bbase + ray;

  float* s_q = sm + OFF_Q;      // fp32; aliased as ao after head loop
  float* s_k = sm + OFF_K;
  float* s_v = sm + OFF_V;
  float* s_ao = sm + OFF_Q;     // ALIAS (disjoint lifetime with q)
  __half* acth = (__half*)(sm + OFF_ACTH);
  __half* actl = (__half*)(sm + OFF_ACTL);
  __half* xh = (__half*)(sm + OFF_XH);
  __half* xl = (__half*)(sm + OFF_XL);
  uint* uacth = (uint*)acth;
  uint* uactl = (uint*)actl;
  uint* uxh = (uint*)xh;
  uint* uxl = (uint*)xl;

  // weight tile sets: set0 = tiles 0..5 (3 hi/lo pairs), w3 = tiles 6,7, set1 = 8..13
  uint* wsh[2][3]; uint* wsl[2][3];
  #pragma unroll
  for (int s = 0; s < 2; s++)
    #pragma unroll
    for (int j = 0; j < 3; j++) {
      wsh[s][j] = (uint*)(sm + OFF_WB + (s * 8 + j * 2) * TILE_F);
      wsl[s][j] = (uint*)(sm + OFF_WB + (s * 8 + j * 2 + 1) * TILE_F);
    }
  uint* w3h = (uint*)(sm + OFF_WB + 6 * TILE_F);
  uint* w3l = (uint*)(sm + OFF_WB + 7 * TILE_F);
  float* my_p = sm + OFF_P + ray * 64;

  // ---------------- stage 0: act = relu(latent @ W1 + b1), K=512 ----------------
  {
    stage_w_h(p.W1, 64, (__half*)wsh[0][0], (__half*)wsl[0][0], tid);
    STAGE_LAT(acth, actl, 0);
    __syncthreads();
    float c[2][4] = {};
    for (int kc = 0; kc < 8; kc++) {
      const uint* lbh = (kc & 1) ? uxh : uacth;
      const uint* lbl = (kc & 1) ? uxl : uactl;
      const uint* wbh = (kc & 1) ? wsh[1][0] : wsh[0][0];
      const uint* wbl = (kc & 1) ? wsl[1][0] : wsl[0][0];
      if (kc < 7) {
        stage_w_h(p.W1 + (kc + 1) * 4096, 64,
                  (kc & 1) ? (__half*)wsh[0][0] : (__half*)wsh[1][0],
                  (kc & 1) ? (__half*)wsl[0][0] : (__half*)wsl[1][0], tid);
        if (kc & 1) STAGE_LAT(acth, actl, kc + 1);
        else        STAGE_LAT(xh, xl, kc + 1);
      }
      gemm_acc(lbh, lbl, wbh, wbl, lane, mt, nq, c);
      __syncthreads();
    }
    store_c_h(uacth, uactl, lane, mt, nq, c, p.b1, 1);
  }
  __syncthreads();
  // stage layer0 head0 QKV into set0 (serial)
  stage_w_h(p.Wq, 256, (__half*)wsh[0][0], (__half*)wsl[0][0], tid);
  stage_w_h(p.Wk, 256, (__half*)wsh[0][1], (__half*)wsl[0][1], tid);
  stage_w_h(p.Wv, 256, (__half*)wsh[0][2], (__half*)wsl[0][2], tid);
  __syncthreads();

  // ---------------- 4 transformer layers ----------------
  for (int l = 0; l < 4; l++) {
    float co[2][2][4] = {};   // out-proj accumulator (warps 0-7)
    for (int h = 0; h < 4; h++) {
      const int s = (l + h) & 1;
      if (warp < 8) {
        // fused QKV, m32n16
        float cq[2][2][4] = {}, ck[2][2][4] = {}, cv[2][2][4] = {};
        gemm3_8(uacth, uactl,
                wsh[s][0], wsl[s][0], wsh[s][1], wsl[s][1], wsh[s][2], wsl[s][2],
                lane, mh, nq8, cq, ck, cv);
        #pragma unroll
        for (int mt2 = 0; mt2 < 2; mt2++) {
          store_c(s_q, lane, mh * 2 + mt2, nq8, cq[mt2],
                  p.bq + l * 256 + h * 64, 0, nullptr, nullptr);
          store_c(s_k, lane, mh * 2 + mt2, nq8, ck[mt2],
                  p.bk + l * 256 + h * 64, 0, nullptr, nullptr);
          store_c(s_v, lane, mh * 2 + mt2, nq8, cv[mt2],
                  p.bv + l * 256 + h * 64, 0, nullptr, nullptr);
        }
      } else {
        // staging warps: Wo(h) + next weights into the other set
        stage_w_h8(p.Wo + l * 16384 + h * 4096, 64, (__half*)w3h, (__half*)w3l, t8);
        if (h < 3) {
          stage_w_h8(p.Wq + l * 16384 + (h + 1) * 64, 256,
                     (__half*)wsh[s ^ 1][0], (__half*)wsl[s ^ 1][0], t8);
          stage_w_h8(p.Wk + l * 16384 + (h + 1) * 64, 256,
                     (__half*)wsh[s ^ 1][1], (__half*)wsl[s ^ 1][1], t8);
          stage_w_h8(p.Wv + l * 16384 + (h + 1) * 64, 256,
                     (__half*)wsh[s ^ 1][2], (__half*)wsl[s ^ 1][2], t8);
        } else {
          stage_w_h8(p.fW1 + l * 4096, 64,
                     (__half*)wsh[s ^ 1][0], (__half*)wsl[s ^ 1][0], t8);
          stage_w_h8(p.fW2 + l * 4096, 64,
                     (__half*)wsh[s ^ 1][1], (__half*)wsl[s ^ 1][1], t8);
        }
      }
      __syncthreads();   // (A) QKV + staged weights visible

      // ---- attention (scalar fp32): warp pair per ray, 4 q-rows each ----
      {
        const float* qb = s_q + ray * 8 * S_A;
        const float* kb = s_k + ray * 8 * S_A;
        const float* vb = s_v + ray * 8 * S_A;
        int idx = half_ * 32 + lane;
        int qi = idx >> 3, ki = idx & 7;
        const float* qr = qb + qi * S_A;
        const float* kr = kb + ki * S_A;
        ull acc = pack2(0.f, 0.f);
        #pragma unroll
        for (int j = 0; j < 64; j += 4) {
          ulonglong2 qq = *(const ulonglong2*)(qr + j);
          ulonglong2 kk2 = *(const ulonglong2*)(kr + j);
          acc = ffma2(qq.x, kk2.x, acc);
          acc = ffma2(qq.y, kk2.y, acc);
        }
        float2 t = unpack2(acc);
        float sc = (t.x + t.y) * 0.125f;
        float m = sc;
        m = fmaxf(m, __shfl_xor_sync(0xffffffffu, m, 1));
        m = fmaxf(m, __shfl_xor_sync(0xffffffffu, m, 2));
        m = fmaxf(m, __shfl_xor_sync(0xffffffffu, m, 4));
        float e = __expf(sc - m);
        float se = e;
        se += __shfl_xor_sync(0xffffffffu, se, 1);
        se += __shfl_xor_sync(0xffffffffu, se, 2);
        se += __shfl_xor_sync(0xffffffffu, se, 4);
        float pr = __fdividef(e, se);
        my_p[idx] = pr;
        p.o_attn[(size_t)b * 1024 + (size_t)l * 256 + h * 64 + idx] = pr;
        __syncwarp();
        float cx[8];
        #pragma unroll
        for (int i = 0; i < 8; i++) cx[i] = 0.f;
        #pragma unroll
        for (int kj = 0; kj < 8; kj++) {
          float vx = vb[kj * S_A + lane];
          float vy = vb[kj * S_A + lane + 32];
          #pragma unroll
          for (int ql = 0; ql < 4; ql++) {
            float pk = my_p[(rb + ql) * 8 + kj];
            cx[2 * ql] = fmaf(pk, vx, cx[2 * ql]);
            cx[2 * ql + 1] = fmaf(pk, vy, cx[2 * ql + 1]);
          }
        }
        #pragma unroll
        for (int ql = 0; ql < 4; ql++) {
          int row = ray * 8 + rb + ql;
          __half hh, hl;
          hsplit1(cx[2 * ql], hh, hl);
          xh[row * S_H + lane] = hh; xl[row * S_H + lane] = hl;
          hsplit1(cx[2 * ql + 1], hh, hl);
          xh[row * S_H + lane + 32] = hh; xl[row * S_H + lane + 32] = hl;
        }
      }
      __syncthreads();   // (B) ctx visible

      if (warp < 8) {
        // out-proj: co += ctx @ Wo_h (m32n16)
        gemm_8(uxh, uxl, w3h, w3l, lane, mh, nq8, co);
      } else if (h == 3 && l < 3) {
        // stage next-layer head0 QKV into set (l+1)&1 (freed after sync A of h3)
        const int sn = (l + 1) & 1;
        stage_w_h8(p.Wq + (l + 1) * 16384, 256, (__half*)wsh[sn][0], (__half*)wsl[sn][0], t8);
        stage_w_h8(p.Wk + (l + 1) * 16384, 256, (__half*)wsh[sn][1], (__half*)wsl[sn][1], t8);
        stage_w_h8(p.Wv + (l + 1) * 16384, 256, (__half*)wsh[sn][2], (__half*)wsl[sn][2], t8);
      }
      __syncthreads();   // (C) out-proj done; w3 free for next head's staging
    }  // heads

    if (warp < 8) {
      #pragma unroll
      for (int mt2 = 0; mt2 < 2; mt2++)
        store_c(s_ao, lane, mh * 2 + mt2, nq8, co[mt2], p.bo + l * 64, 0,
                nullptr, nullptr);
    }
    __syncthreads();
    // LN1: act = LN(ao + act)
    ln4(s_ao + (ray * 8 + rb) * S_A,
        acth + (ray * 8 + rb) * S_H, actl + (ray * 8 + rb) * S_H,
        p.g1 + l * 64, p.be1 + l * 64, lane,
        acth + (ray * 8 + rb) * S_H, actl + (ray * 8 + rb) * S_H);
    __syncthreads();
    // FF1: fW1 in set[l&1] slot0
    {
      const int sf = l & 1;
      float c[2][4] = {};
      gemm_acc(uacth, uactl, wsh[sf][0], wsl[sf][0], lane, mt, nq, c);
      store_c_h(uxh, uxl, lane, mt, nq, c, p.fb1 + l * 64, 1);
    }
    __syncthreads();
    // FF2 + residual(act halves) -> ao fp32
    {
      const int sf = l & 1;
      float c[2][4] = {};
      gemm_acc(uxh, uxl, wsh[sf][1], wsl[sf][1], lane, mt, nq, c);
      store_c(s_ao, lane, mt, nq, c, p.fb2 + l * 64, 0, uacth, uactl);
    }
    __syncthreads();
    // LN2: act = LN(ao)
    ln4(s_ao + (ray * 8 + rb) * S_A, nullptr, nullptr,
        p.g2 + l * 64, p.be2 + l * 64, lane,
        acth + (ray * 8 + rb) * S_H, actl + (ray * 8 + rb) * S_H);
    __syncthreads();
  }  // layers

  // ---------------- sigma & out ----------------
  {
    const __half* ah = acth + ray * 8 * S_H;
    const __half* al = actl + ray * 8 * S_H;
    if (half_ == 0) {
      float m0 = -1e30f, m1 = -1e30f;
      #pragma unroll
      for (int s = 0; s < 8; s++) {
        m0 = fmaxf(m0, __half2float(ah[s * S_H + lane]) + __half2float(al[s * S_H + lane]));
        m1 = fmaxf(m1, __half2float(ah[s * S_H + lane + 32]) + __half2float(al[s * S_H + lane + 32]));
      }
      float part = m0 * __ldg(p.Ws + lane) + m1 * __ldg(p.Ws + lane + 32);
      #pragma unroll
      for (int o = 16; o > 0; o >>= 1) part += __shfl_xor_sync(0xffffffffu, part, o);
      if (lane == 0) p.o_sigma[b] = part + __ldg(p.bs);
    }
    #pragma unroll
    for (int s = 0; s < 4; s++) {
      int row = rb + s;
      p.o_out[(size_t)b * 512 + row * 64 + lane] =
          __half2float(ah[row * S_H + lane]) + __half2float(al[row * S_H + lane]);
      p.o_out[(size_t)b * 512 + row * 64 + lane + 32] =
          __half2float(ah[row * S_H + lane + 32]) + __half2float(al[row * S_H + lane + 32]);
    }
  }

  // ---------------- cross attention + color ----------------
  float* qr = s_ao + ray * S_A;  // query row (fp32; ao free here)
  if (half_ == 0) {
    qr[lane] = p.query[(size_t)b * 64 + lane];
    qr[lane + 32] = p.query[(size_t)b * 64 + lane + 32];
  }

  uint* cw0h = wsh[0][0]; uint* cw0l = wsl[0][0];   // cWk
  uint* cw1h = wsh[0][1]; uint* cw1l = wsl[0][1];   // cWv
  uint* cw2h = wsh[0][2]; uint* cw2l = wsl[0][2];   // cWo
  float ca0 = 0.f, ca1 = 0.f;
  for (int h = 0; h < 4; h++) {
    __syncthreads();
    stage_w_h(p.cWk + h * 64, 256, (__half*)cw0h, (__half*)cw0l, tid);
    stage_w_h(p.cWv + h * 64, 256, (__half*)cw1h, (__half*)cw1l, tid);
    stage_w_h(p.cWq + h * 64, 256, (__half*)w3h, (__half*)w3l, tid);
    stage_w_h(p.cWo + h * 4096, 64, (__half*)cw2h, (__half*)cw2l, tid);
    __syncthreads();
    {
      float ck[2][4] = {}, cv[2][4] = {};
      gemm2_acc(uacth, uactl, cw0h, cw0l, cw1h, cw1l, lane, mt, nq, ck, cv);
      store_c(s_k, lane, mt, nq, ck, p.cbk + h * 64, 0, nullptr, nullptr);
      store_c(s_v, lane, mt, nq, cv, p.cbv + h * 64, 0, nullptr, nullptr);
    }
    __syncthreads();
    if (half_ == 0) {
      float cq0 = __ldg(p.cbq + h * 64 + lane);
      float cq1 = __ldg(p.cbq + h * 64 + lane + 32);
      #pragma unroll 8
      for (int k = 0; k < 64; k += 2) {
        int wi = k >> 1;
        float a0 = qr[k], a1 = qr[k + 1];
        float2 wv0 = h2f(w3h[lane * 36 + wi]);
        float2 wl0_ = h2f(w3l[lane * 36 + wi]);
        float2 wv1 = h2f(w3h[(lane + 32) * 36 + wi]);
        float2 wl1_ = h2f(w3l[(lane + 32) * 36 + wi]);
        cq0 = fmaf(a0, wv0.x + wl0_.x, cq0);
        cq0 = fmaf(a1, wv0.y + wl0_.y, cq0);
        cq1 = fmaf(a0, wv1.x + wl1_.x, cq1);
        cq1 = fmaf(a1, wv1.y + wl1_.y, cq1);
      }
      const float* kb = s_k + ray * 8 * S_A;
      const float* vb = s_v + ray * 8 * S_A;
      float e[8];
      #pragma unroll
      for (int k = 0; k < 8; k++) {
        float pk = cq0 * kb[k * S_A + lane] + cq1 * kb[k * S_A + lane + 32];
        #pragma unroll
        for (int o = 16; o > 0; o >>= 1) pk += __shfl_xor_sync(0xffffffffu, pk, o);
        e[k] = pk * 0.125f;
      }
      float mm = e[0];
      #pragma unroll
      for (int k = 1; k < 8; k++) mm = fmaxf(mm, e[k]);
      float prb[8], sum = 0.f;
      #pragma unroll
      for (int k = 0; k < 8; k++) { prb[k] = __expf(e[k] - mm); sum += prb[k]; }
      float inv = __fdividef(1.f, sum);
      float cx0 = 0.f, cx1 = 0.f;
      #pragma unroll
      for (int k = 0; k < 8; k++) {
        float pk = prb[k] * inv;
        cx0 = fmaf(pk, vb[k * S_A + lane], cx0);
        cx1 = fmaf(pk, vb[k * S_A + lane + 32], cx1);
      }
      my_p[lane] = cx0;
      my_p[lane + 32] = cx1;
      __syncwarp();
      if (h == 0) { ca0 = __ldg(p.cbo + lane); ca1 = __ldg(p.cbo + lane + 32); }
      #pragma unroll 8
      for (int k = 0; k < 64; k += 2) {
        int wi = k >> 1;
        float a0 = my_p[k], a1 = my_p[k + 1];
        float2 wv0 = h2f(cw2h[lane * 36 + wi]);
        float2 wl0_ = h2f(cw2l[lane * 36 + wi]);
        float2 wv1 = h2f(cw2h[(lane + 32) * 36 + wi]);
        float2 wl1_ = h2f(cw2l[(lane + 32) * 36 + wi]);
        ca0 = fmaf(a0, wv0.x + wl0_.x, ca0);
        ca0 = fmaf(a1, wv0.y + wl0_.y, ca0);
        ca1 = fmaf(a0, wv1.x + wl1_.x, ca1);
        ca1 = fmaf(a1, wv1.y + wl1_.y, ca1);
      }
    }
  }

  if (half_ == 0) {
    float r0 = fmaxf(ca0, 0.f), r1 = fmaxf(ca1, 0.f);
    #pragma unroll
    for (int t = 0; t < 3; t++) {
      float part = r0 * __ldg(p.Wc + lane * 3 + t) + r1 * __ldg(p.Wc + (lane + 32) * 3 + t);
      #pragma unroll
      for (int o = 16; o > 0; o >>= 1) part += __shfl_xor_sync(0xffffffffu, part, o);
      if (lane == 0) p.o_color[(size_t)b * 3 + t] = part + __ldg(p.bc + t);
    }
  }
}

extern "C" void kernel_launch(void* const* d_in, const int* in_sizes, int n_in,
                              void* d_out, int out_size) {
  Params p;
  p.query = (const float*)d_in[0];
  p.latent = (const float*)d_in[1];
  p.W1 = (const float*)d_in[2];
  p.b1 = (const float*)d_in[3];
  p.Wq = (const float*)d_in[4];
  p.bq = (const float*)d_in[5];
  p.Wk = (const float*)d_in[6];
  p.bk = (const float*)d_in[7];
  p.Wv = (const float*)d_in[8];
  p.bv = (const float*)d_in[9];
  p.Wo = (const float*)d_in[10];
  p.bo = (const float*)d_in[11];
  p.fW1 = (const float*)d_in[12];
  p.fb1 = (const float*)d_in[13];
  p.fW2 = (const float*)d_in[14];
  p.fb2 = (const float*)d_in[15];
  p.g1 = (const float*)d_in[16];
  p.be1 = (const float*)d_in[17];
  p.g2 = (const float*)d_in[18];
  p.be2 = (const float*)d_in[19];
  p.cWq = (const float*)d_in[20];
  p.cbq = (const float*)d_in[21];
  p.cWk = (const float*)d_in[22];
  p.cbk = (const float*)d_in[23];
  p.cWv = (const float*)d_in[24];
  p.cbv = (const float*)d_in[25];
  p.cWo = (const float*)d_in[26];
  p.cbo = (const float*)d_in[27];
  p.Wc = (const float*)d_in[28];
  p.bc = (const float*)d_in[29];
  p.Ws = (const float*)d_in[30];
  p.bs = (const float*)d_in[31];

  float* o = (float*)d_out;
  p.o_color = o;                                    // [B,1,3]
  p.o_sigma = o + (size_t)B_TOTAL * 3;              // [B,1]
  p.o_out = o + (size_t)B_TOTAL * 4;                // [B,8,64]
  p.o_attn = o + (size_t)B_TOTAL * 4 + (size_t)B_TOTAL * 512;  // [B,4,4,8,8]

  cudaFuncSetAttribute(rt_kernel, cudaFuncAttributeMaxDynamicSharedMemorySize,
                       SMEM_BYTES);
  rt_kernel<<<NBLOCKS, NTHREADS, SMEM_BYTES>>>(p);
}

// round 15
// speedup vs baseline: 1.1036x; 1.1036x over previous
#include <cuda_runtime.h>
#include <cuda_fp16.h>

typedef unsigned long long ull;
typedef unsigned int uint;

#define NTHREADS 512
#define RAYS 8
#define NBLOCKS 4096
#define B_TOTAL 32768
#define S_A 68      // fp32 tile stride (floats)
#define S_H 72      // half tile stride (halves); word stride 36

// smem offsets (floats); half tile = 64*72 halves = 2304 floats
#define OFF_Q    0
#define OFF_K    4352
#define OFF_V    8704
#define OFF_AO   13056
#define OFF_ACTH 17408
#define OFF_ACTL 19712
#define OFF_XH   22016
#define OFF_XL   24320
#define OFF_W0H  26624
#define OFF_W0L  28928
#define OFF_W1H  31232
#define OFF_W1L  33536
#define OFF_W2H  35840
#define OFF_W2L  38144
#define OFF_W3H  40448
#define OFF_W3L  42752
#define OFF_P    45056
#define SMEM_FLOATS (45056 + 512)   // 182272 B
#define SMEM_BYTES (SMEM_FLOATS * 4)

struct Params {
  const float *query, *latent, *W1, *b1;
  const float *Wq, *bq, *Wk, *bk, *Wv, *bv, *Wo, *bo;
  const float *fW1, *fb1, *fW2, *fb2, *g1, *be1, *g2, *be2;
  const float *cWq, *cbq, *cWk, *cbk, *cWv, *cbv, *cWo, *cbo;
  const float *Wc, *bc, *Ws, *bs;
  float *o_color, *o_sigma, *o_out, *o_attn;
};

// ---------------- helpers ----------------
__device__ __forceinline__ ull ffma2(ull a, ull b, ull c) {
  ull d;
  asm("fma.rn.f32x2 %0, %1, %2, %3;" : "=l"(d) : "l"(a), "l"(b), "l"(c));
  return d;
}
__device__ __forceinline__ ull pack2(float lo, float hi) {
  ull d;
  asm("mov.b64 %0, {%1, %2};" : "=l"(d) : "f"(lo), "f"(hi));
  return d;
}
__device__ __forceinline__ float2 unpack2(ull v) {
  float lo, hi;
  asm("mov.b64 {%0, %1}, %2;" : "=f"(lo), "=f"(hi) : "l"(v));
  return make_float2(lo, hi);
}
__device__ __forceinline__ uint hpackr(float a, float b, float& ra, float& rb) {
  __half ha = __float2half_rn(a), hb = __float2half_rn(b);
  ra = a - __half2float(ha);
  rb = b - __half2float(hb);
  __half2 p = __halves2half2(ha, hb);
  return *(uint*)&p;
}
__device__ __forceinline__ uint hpack(float a, float b) {
  __half2 p = __halves2half2(__float2half_rn(a), __float2half_rn(b));
  return *(uint*)&p;
}
__device__ __forceinline__ float2 h2f(uint u) {
  return __half22float2(*(__half2*)&u);
}
__device__ __forceinline__ void hsplit1(float x, __half& h, __half& l) {
  h = __float2half_rn(x);
  l = __float2half_rn(x - __half2float(h));
}

__device__ __forceinline__ void mma16(float c[4], uint a0, uint a1, uint a2, uint a3,
                                      uint b0, uint b1) {
  asm("mma.sync.aligned.m16n8k16.row.col.f32.f16.f16.f32 "
      "{%0,%1,%2,%3},{%4,%5,%6,%7},{%8,%9},{%0,%1,%2,%3};"
      : "+f"(c[0]), "+f"(c[1]), "+f"(c[2]), "+f"(c[3])
      : "r"(a0), "r"(a1), "r"(a2), "r"(a3), "r"(b0), "r"(b1));
}

struct AF { uint h[4], l[4]; };
__device__ __forceinline__ AF load_a(const uint* __restrict__ Ah,
                                     const uint* __restrict__ Al,
                                     int lane, int mt, int kk) {
  const int grp = lane >> 2, kq = lane & 3;
  const int base = (mt * 16 + grp) * 36 + kk * 8 + kq;
  AF f;
  f.h[0] = Ah[base];
  f.h[1] = Ah[base + 8 * 36];
  f.h[2] = Ah[base + 4];
  f.h[3] = Ah[base + 8 * 36 + 4];
  f.l[0] = Al[base];
  f.l[1] = Al[base + 8 * 36];
  f.l[2] = Al[base + 4];
  f.l[3] = Al[base + 8 * 36 + 4];
  return f;
}
__device__ __forceinline__ void mma3h(float c[4], const AF& a,
                                      uint wh0, uint wh1, uint wl0, uint wl1) {
  mma16(c, a.h[0], a.h[1], a.h[2], a.h[3], wh0, wh1);
  mma16(c, a.l[0], a.l[1], a.l[2], a.l[3], wh0, wh1);
  mma16(c, a.h[0], a.h[1], a.h[2], a.h[3], wl0, wl1);
}

// 16-warp m16n16 single gemm with kk-parity accumulator split (4 chains)
__device__ __forceinline__ void gemm_acc(const uint* Ah, const uint* Al,
                                         const uint* Wh, const uint* Wl,
                                         int lane, int mt, int nq, float c[2][4]) {
  const int grp = lane >> 2, kq = lane & 3;
  float cB[2][4] = {};
  #pragma unroll
  for (int kk = 0; kk < 4; kk++) {
    AF a = load_a(Ah, Al, lane, mt, kk);
    const int off = (nq * 16 + grp) * 36 + kk * 8 + kq;
    #pragma unroll
    for (int t = 0; t < 2; t++) {
      const int o = off + t * 8 * 36;
      if (kk & 1) mma3h(cB[t], a, Wh[o], Wh[o + 4], Wl[o], Wl[o + 4]);
      else        mma3h(c[t],  a, Wh[o], Wh[o + 4], Wl[o], Wl[o + 4]);
    }
  }
  #pragma unroll
  for (int t = 0; t < 2; t++)
    #pragma unroll
    for (int i = 0; i < 4; i++) c[t][i] += cB[t][i];
}

// 16-warp fused 2-matrix gemm, kk-parity split (8 chains)
__device__ __forceinline__ void gemm2_acc(const uint* Ah, const uint* Al,
                                          const uint* W0h, const uint* W0l,
                                          const uint* W1h, const uint* W1l,
                                          int lane, int mt, int nq,
                                          float c0[2][4], float c1[2][4]) {
  const int grp = lane >> 2, kq = lane & 3;
  float c0B[2][4] = {}, c1B[2][4] = {};
  #pragma unroll
  for (int kk = 0; kk < 4; kk++) {
    AF a = load_a(Ah, Al, lane, mt, kk);
    const int off = (nq * 16 + grp) * 36 + kk * 8 + kq;
    #pragma unroll
    for (int t = 0; t < 2; t++) {
      const int o = off + t * 8 * 36;
      if (kk & 1) {
        mma3h(c0B[t], a, W0h[o], W0h[o + 4], W0l[o], W0l[o + 4]);
        mma3h(c1B[t], a, W1h[o], W1h[o + 4], W1l[o], W1l[o + 4]);
      } else {
        mma3h(c0[t], a, W0h[o], W0h[o + 4], W0l[o], W0l[o + 4]);
        mma3h(c1[t], a, W1h[o], W1h[o + 4], W1l[o], W1l[o + 4]);
      }
    }
  }
  #pragma unroll
  for (int t = 0; t < 2; t++)
    #pragma unroll
    for (int i = 0; i < 4; i++) { c0[t][i] += c0B[t][i]; c1[t][i] += c1B[t][i]; }
}

// 16-warp fused QKV (6 chains; no split — sets register high-water mark)
__device__ __forceinline__ void gemm3_acc(const uint* Ah, const uint* Al,
                                          const uint* W0h, const uint* W0l,
                                          const uint* W1h, const uint* W1l,
                                          const uint* W2h, const uint* W2l,
                                          int lane, int mt, int nq,
                                          float c0[2][4], float c1[2][4],
                                          float c2[2][4]) {
  const int grp = lane >> 2, kq = lane & 3;
  #pragma unroll
  for (int kk = 0; kk < 4; kk++) {
    AF a = load_a(Ah, Al, lane, mt, kk);
    const int off = (nq * 16 + grp) * 36 + kk * 8 + kq;
    #pragma unroll
    for (int t = 0; t < 2; t++) {
      const int o = off + t * 8 * 36;
      mma3h(c0[t], a, W0h[o], W0h[o + 4], W0l[o], W0l[o + 4]);
      mma3h(c1[t], a, W1h[o], W1h[o + 4], W1l[o], W1l[o + 4]);
      mma3h(c2[t], a, W2h[o], W2h[o + 4], W2l[o], W2l[o + 4]);
    }
  }
}

__device__ __forceinline__ void store_c(float* D, int lane, int mt, int nq,
                                        const float c[2][4], const float* bias,
                                        int do_relu, const uint* rh, const uint* rl) {
  const int grp = lane >> 2, kq = lane & 3;
  const int r = mt * 16 + grp;
  #pragma unroll
  for (int t = 0; t < 2; t++) {
    int col = nq * 16 + t * 8 + 2 * kq;
    float b0 = __ldg(bias + col), b1 = __ldg(bias + col + 1);
    float v0 = c[t][0] + b0, v1 = c[t][1] + b1;
    float v2 = c[t][2] + b0, v3 = c[t][3] + b1;
    if (rh) {
      int w0 = r * 36 + (col >> 1), w1 = (r + 8) * 36 + (col >> 1);
      float2 fh0 = h2f(rh[w0]), fl0 = h2f(rl[w0]);
      float2 fh1 = h2f(rh[w1]), fl1 = h2f(rl[w1]);
      v0 += fh0.x + fl0.x; v1 += fh0.y + fl0.y;
      v2 += fh1.x + fl1.x; v3 += fh1.y + fl1.y;
    }
    if (do_relu) {
      v0 = fmaxf(v0, 0.f); v1 = fmaxf(v1, 0.f);
      v2 = fmaxf(v2, 0.f); v3 = fmaxf(v3, 0.f);
    }
    *(float2*)(D + r * S_A + col) = make_float2(v0, v1);
    *(float2*)(D + (r + 8) * S_A + col) = make_float2(v2, v3);
  }
}

__device__ __forceinline__ void store_c_h(uint* Dh, uint* Dl, int lane, int mt, int nq,
                                          const float c[2][4], const float* bias,
                                          int do_relu) {
  const int grp = lane >> 2, kq = lane & 3;
  const int r = mt * 16 + grp;
  #pragma unroll
  for (int t = 0; t < 2; t++) {
    int col = nq * 16 + t * 8 + 2 * kq;
    float b0 = __ldg(bias + col), b1 = __ldg(bias + col + 1);
    float v0 = c[t][0] + b0, v1 = c[t][1] + b1;
    float v2 = c[t][2] + b0, v3 = c[t][3] + b1;
    if (do_relu) {
      v0 = fmaxf(v0, 0.f); v1 = fmaxf(v1, 0.f);
      v2 = fmaxf(v2, 0.f); v3 = fmaxf(v3, 0.f);
    }
    float ra, rb;
    uint h01 = hpackr(v0, v1, ra, rb);
    uint l01 = hpack(ra, rb);
    Dh[r * 36 + (col >> 1)] = h01;
    Dl[r * 36 + (col >> 1)] = l01;
    uint h23 = hpackr(v2, v3, ra, rb);
    uint l23 = hpack(ra, rb);
    Dh[(r + 8) * 36 + (col >> 1)] = h23;
    Dl[(r + 8) * 36 + (col >> 1)] = l23;
  }
}

// stage 64x64 fp32 weight [k][n] -> transposed [n][k] half hi/lo tiles
__device__ __forceinline__ void stage_w_h(const float* __restrict__ src, int stride,
                                          __half* __restrict__ dh,
                                          __half* __restrict__ dl, int tid) {
  #pragma unroll
  for (int it = 0; it < 2; it++) {
    int i = tid + it * NTHREADS;
    int n = i & 63, k4 = (i >> 6) << 2;
    float v0 = src[(k4 + 0) * stride + n];
    float v1 = src[(k4 + 1) * stride + n];
    float v2 = src[(k4 + 2) * stride + n];
    float v3 = src[(k4 + 3) * stride + n];
    float r0, r1, r2, r3;
    uint2 hw, lw;
    hw.x = hpackr(v0, v1, r0, r1);
    hw.y = hpackr(v2, v3, r2, r3);
    lw.x = hpack(r0, r1);
    lw.y = hpack(r2, r3);
    *(uint2*)(dh + n * S_H + k4) = hw;
    *(uint2*)(dl + n * S_H + k4) = lw;
  }
}

__device__ __forceinline__ void ln4(const float* s1, const __half* s2h,
                                    const __half* s2l, const float* g,
                                    const float* be, int lane,
                                    __half* dh, __half* dl) {
  float gg0 = __ldg(g + lane), gg1 = __ldg(g + lane + 32);
  float bb0 = __ldg(be + lane), bb1 = __ldg(be + lane + 32);
  #pragma unroll
  for (int s = 0; s < 4; s++) {
    float x0 = s1[s * S_A + lane];
    float x1 = s1[s * S_A + lane + 32];
    if (s2h) {
      x0 += __half2float(s2h[s * S_H + lane]) + __half2float(s2l[s * S_H + lane]);
      x1 += __half2float(s2h[s * S_H + lane + 32]) + __half2float(s2l[s * S_H + lane + 32]);
    }
    float sum = x0 + x1;
    #pragma unroll
    for (int o = 16; o > 0; o >>= 1) sum += __shfl_xor_sync(0xffffffffu, sum, o);
    float mean = sum * 0.015625f;
    float d0 = x0 - mean, d1 = x1 - mean;
    float vs = d0 * d0 + d1 * d1;
    #pragma unroll
    for (int o = 16; o > 0; o >>= 1) vs += __shfl_xor_sync(0xffffffffu, vs, o);
    float rstd = rsqrtf(vs * 0.015625f + 1e-5f);
    float y0 = d0 * rstd * gg0 + bb0;
    float y1 = d1 * rstd * gg1 + bb1;
    __half h, l;
    hsplit1(y0, h, l);
    dh[s * S_H + lane] = h; dl[s * S_H + lane] = l;
    hsplit1(y1, h, l);
    dh[s * S_H + lane + 32] = h; dl[s * S_H + lane + 32] = l;
  }
}

#define STAGE_LAT(DH, DL, KC)                                                  \
  do {                                                                         \
    _Pragma("unroll")                                                          \
    for (int it_ = 0; it_ < 2; it_++) {                                        \
      int i_ = tid + it_ * NTHREADS;                                           \
      int row_ = i_ >> 4, j_ = (i_ & 15) * 4;                                  \
      float4 v_ = *(const float4*)(p.latent + (size_t)(bbase + (row_ >> 3)) * 4096 + \
                                   (row_ & 7) * 512 + (KC) * 64 + j_);         \
      float r0_, r1_, r2_, r3_;                                                \
      uint2 hw_, lw_;                                                          \
      hw_.x = hpackr(v_.x, v_.y, r0_, r1_);                                    \
      hw_.y = hpackr(v_.z, v_.w, r2_, r3_);                                    \
      lw_.x = hpack(r0_, r1_);                                                 \
      lw_.y = hpack(r2_, r3_);                                                 \
      *(uint2*)((DH) + row_ * S_H + j_) = hw_;                                 \
      *(uint2*)((DL) + row_ * S_H + j_) = lw_;                                 \
    }                                                                          \
  } while (0)

__global__ void __launch_bounds__(NTHREADS, 1) rt_kernel(Params p) {
  extern __shared__ float sm[];
  const int tid = threadIdx.x;
  const int warp = tid >> 5, lane = tid & 31;
  const int mt = warp & 3, nq = warp >> 2;
  const int ray = warp & 7, half_ = warp >> 3, rb = half_ * 4;
  const int bbase = blockIdx.x * RAYS;
  const int b = bbase + ray;

  float* s_q = sm + OFF_Q;
  float* s_k = sm + OFF_K;
  float* s_v = sm + OFF_V;
  float* s_ao = sm + OFF_AO;
  __half* acth = (__half*)(sm + OFF_ACTH);
  __half* actl = (__half*)(sm + OFF_ACTL);
  __half* xh = (__half*)(sm + OFF_XH);
  __half* xl = (__half*)(sm + OFF_XL);
  uint* uacth = (uint*)acth;
  uint* uactl = (uint*)actl;
  uint* uxh = (uint*)xh;
  uint* uxl = (uint*)xl;
  uint* w0h = (uint*)(sm + OFF_W0H); uint* w0l = (uint*)(sm + OFF_W0L);
  uint* w1h = (uint*)(sm + OFF_W1H); uint* w1l = (uint*)(sm + OFF_W1L);
  uint* w2h = (uint*)(sm + OFF_W2H); uint* w2l = (uint*)(sm + OFF_W2L);
  uint* w3h = (uint*)(sm + OFF_W3H); uint* w3l = (uint*)(sm + OFF_W3L);
  float* my_p = sm + OFF_P + ray * 64;

  // ---------------- stage 0: act = relu(latent @ W1 + b1), K=512 ----------------
  // ping-pong W1 chunks between w0 and w1 pairs; prestage layer0 Wk/Wv into w2/w3
  // during the last two iterations (those slots are idle here).
  {
    stage_w_h(p.W1, 64, (__half*)w0h, (__half*)w0l, tid);
    STAGE_LAT(acth, actl, 0);
    __syncthreads();
    float c[2][4] = {};
    for (int kc = 0; kc < 8; kc++) {
      const uint* lbh = (kc & 1) ? uxh : uacth;
      const uint* lbl = (kc & 1) ? uxl : uactl;
      const uint* wbh = (kc & 1) ? w1h : w0h;
      const uint* wbl = (kc & 1) ? w1l : w0l;
      if (kc < 7) {
        stage_w_h(p.W1 + (kc + 1) * 4096, 64,
                  (kc & 1) ? (__half*)w0h : (__half*)w1h,
                  (kc & 1) ? (__half*)w0l : (__half*)w1l, tid);
        if (kc & 1) STAGE_LAT(acth, actl, kc + 1);
        else        STAGE_LAT(xh, xl, kc + 1);
      }
      if (kc == 6) stage_w_h(p.Wk, 256, (__half*)w2h, (__half*)w2l, tid);   // layer0 h0 K
      if (kc == 7) stage_w_h(p.Wv, 256, (__half*)w3h, (__half*)w3l, tid);   // layer0 h0 V
      gemm_acc(lbh, lbl, wbh, wbl, lane, mt, nq, c);
      __syncthreads();
    }
    store_c_h(uacth, uactl, lane, mt, nq, c, p.b1, 1);
  }
  // move prestaged K,V into canonical slots? no — just remap head-0 pointers.
  // stage layer0 head0 Q into w0 pair (only one serial staging now)
  stage_w_h(p.Wq, 256, (__half*)w0h, (__half*)w0l, tid);
  __syncthreads();

  // ---------------- 4 transformer layers ----------------
  // Weight slot convention per head: Q->w0, K->w1, V->w2, Wo->w3,
  // EXCEPT layer0 head0 where K->w2, V->w3 (prestaged). Handle via pointers.
  uint *qh = w0h, *ql = w0l, *kh = w1h, *kl = w1l, *vh = w2h, *vl = w2l;
  uint *oh = w3h, *ol = w3l;
  bool first_head = true;   // layer0 h0 uses prestaged layout K->w2,V->w3, Wo deferred
  for (int l = 0; l < 4; l++) {
    float co[2][4] = {};
    for (int h = 0; h < 4; h++) {
      const uint *Kh = kh, *Kl = kl, *Vh = vh, *Vl = vl;
      if (first_head) { Kh = w2h; Kl = w2l; Vh = w3h; Vl = w3l; }
      // fused QKV
      {
        float cq[2][4] = {}, ck[2][4] = {}, cv[2][4] = {};
        gemm3_acc(uacth, uactl, qh, ql, Kh, Kl, Vh, Vl, lane, mt, nq, cq, ck, cv);
        store_c(s_q, lane, mt, nq, cq, p.bq + l * 256 + h * 64, 0, nullptr, nullptr);
        store_c(s_k, lane, mt, nq, ck, p.bk + l * 256 + h * 64, 0, nullptr, nullptr);
        store_c(s_v, lane, mt, nq, cv, p.bv + l * 256 + h * 64, 0, nullptr, nullptr);
      }
      __syncthreads();   // (A) QKV visible; all weight slots now free

      // stage Wo(h) and next-step weights (overlapped with attention below)
      if (first_head) {
        // w2/w3 were K/V; restage everything into canonical slots
        stage_w_h(p.Wo, 64, (__half*)w3h, (__half*)w3l, tid);
        stage_w_h(p.Wq + 64, 256, (__half*)w0h, (__half*)w0l, tid);
        stage_w_h(p.Wk + 64, 256, (__half*)w1h, (__half*)w1l, tid);
        stage_w_h(p.Wv + 64, 256, (__half*)w2h, (__half*)w2l, tid);
        first_head = false;
      } else {
        stage_w_h(p.Wo + l * 16384 + h * 4096, 64, (__half*)w3h, (__half*)w3l, tid);
        if (h < 3) {
          stage_w_h(p.Wq + l * 16384 + (h + 1) * 64, 256, (__half*)w0h, (__half*)w0l, tid);
          stage_w_h(p.Wk + l * 16384 + (h + 1) * 64, 256, (__half*)w1h, (__half*)w1l, tid);
          stage_w_h(p.Wv + l * 16384 + (h + 1) * 64, 256, (__half*)w2h, (__half*)w2l, tid);
        } else {
          stage_w_h(p.fW1 + l * 4096, 64, (__half*)w0h, (__half*)w0l, tid);
          stage_w_h(p.fW2 + l * 4096, 64, (__half*)w1h, (__half*)w1l, tid);
        }
      }

      // ---- attention (scalar fp32): warp pair per ray, 4 q-rows each ----
      {
        const float* qb = s_q + ray * 8 * S_A;
        const float* kb = s_k + ray * 8 * S_A;
        const float* vb = s_v + ray * 8 * S_A;
        int idx = half_ * 32 + lane;
        int qi = idx >> 3, ki = idx & 7;
        const float* qr = qb + qi * S_A;
        const float* kr = kb + ki * S_A;
        ull acc = pack2(0.f, 0.f);
        #pragma unroll
        for (int j = 0; j < 64; j += 4) {
          ulonglong2 qq = *(const ulonglong2*)(qr + j);
          ulonglong2 kk2 = *(const ulonglong2*)(kr + j);
          acc = ffma2(qq.x, kk2.x, acc);
          acc = ffma2(qq.y, kk2.y, acc);
        }
        float2 t = unpack2(acc);
        float sc = (t.x + t.y) * 0.125f;
        float m = sc;
        m = fmaxf(m, __shfl_xor_sync(0xffffffffu, m, 1));
        m = fmaxf(m, __shfl_xor_sync(0xffffffffu, m, 2));
        m = fmaxf(m, __shfl_xor_sync(0xffffffffu, m, 4));
        float e = __expf(sc - m);
        float se = e;
        se += __shfl_xor_sync(0xffffffffu, se, 1);
        se += __shfl_xor_sync(0xffffffffu, se, 2);
        se += __shfl_xor_sync(0xffffffffu, se, 4);
        float pr = __fdividef(e, se);
        my_p[idx] = pr;
        p.o_attn[(size_t)b * 1024 + (size_t)l * 256 + h * 64 + idx] = pr;
        __syncwarp();
        float cx[8];
        #pragma unroll
        for (int i = 0; i < 8; i++) cx[i] = 0.f;
        #pragma unroll
        for (int kj = 0; kj < 8; kj++) {
          float vx = vb[kj * S_A + lane];
          float vy = vb[kj * S_A + lane + 32];
          #pragma unroll
          for (int qlp = 0; qlp < 4; qlp++) {
            float pk = my_p[(rb + qlp) * 8 + kj];
            cx[2 * qlp] = fmaf(pk, vx, cx[2 * qlp]);
            cx[2 * qlp + 1] = fmaf(pk, vy, cx[2 * qlp + 1]);
          }
        }
        #pragma unroll
        for (int qlp = 0; qlp < 4; qlp++) {
          int row = ray * 8 + rb + qlp;
          __half hh, hl;
          hsplit1(cx[2 * qlp], hh, hl);
          xh[row * S_H + lane] = hh; xl[row * S_H + lane] = hl;
          hsplit1(cx[2 * qlp + 1], hh, hl);
          xh[row * S_H + lane + 32] = hh; xl[row * S_H + lane + 32] = hl;
        }
      }
      __syncthreads();   // (B) ctx + staged weights visible

      // out-proj: co += ctx @ Wo_h
      gemm_acc(uxh, uxl, oh, ol, lane, mt, nq, co);
      // no sync: next head's stores hit q/k/v after its own sync-A readers finish
    }  // heads

    store_c(s_ao, lane, mt, nq, co, p.bo + l * 64, 0, nullptr, nullptr);
    __syncthreads();
    ln4(s_ao + (ray * 8 + rb) * S_A,
        acth + (ray * 8 + rb) * S_H, actl + (ray * 8 + rb) * S_H,
        p.g1 + l * 64, p.be1 + l * 64, lane,
        acth + (ray * 8 + rb) * S_H, actl + (ray * 8 + rb) * S_H);
    __syncthreads();
    // FF1 (fW1 in w0 pair, staged during h==3)
    {
      float c[2][4] = {};
      gemm_acc(uacth, uactl, w0h, w0l, lane, mt, nq, c);
      store_c_h(uxh, uxl, lane, mt, nq, c, p.fb1 + l * 64, 1);
    }
    __syncthreads();
    // FF2 + residual
    {
      float c[2][4] = {};
      gemm_acc(uxh, uxl, w1h, w1l, lane, mt, nq, c);
      store_c(s_ao, lane, mt, nq, c, p.fb2 + l * 64, 0, uacth, uactl);
    }
    __syncthreads();
    ln4(s_ao + (ray * 8 + rb) * S_A, nullptr, nullptr,
        p.g2 + l * 64, p.be2 + l * 64, lane,
        acth + (ray * 8 + rb) * S_H, actl + (ray * 8 + rb) * S_H);
    __syncthreads();
    // stage next layer head0 QKV (serial; small)
    if (l < 3) {
      stage_w_h(p.Wq + (l + 1) * 16384, 256, (__half*)w0h, (__half*)w0l, tid);
      stage_w_h(p.Wk + (l + 1) * 16384, 256, (__half*)w1h, (__half*)w1l, tid);
      stage_w_h(p.Wv + (l + 1) * 16384, 256, (__half*)w2h, (__half*)w2l, tid);
      __syncthreads();
    }
  }  // layers

  // ---------------- sigma & out ----------------
  {
    const __half* ah = acth + ray * 8 * S_H;
    const __half* al = actl + ray * 8 * S_H;
    if (half_ == 0) {
      float m0 = -1e30f, m1 = -1e30f;
      #pragma unroll
      for (int s = 0; s < 8; s++) {
        m0 = fmaxf(m0, __half2float(ah[s * S_H + lane]) + __half2float(al[s * S_H + lane]));
        m1 = fmaxf(m1, __half2float(ah[s * S_H + lane + 32]) + __half2float(al[s * S_H + lane + 32]));
      }
      float part = m0 * __ldg(p.Ws + lane) + m1 * __ldg(p.Ws + lane + 32);
      #pragma unroll
      for (int o = 16; o > 0; o >>= 1) part += __shfl_xor_sync(0xffffffffu, part, o);
      if (lane == 0) p.o_sigma[b] = part + __ldg(p.bs);
    }
    #pragma unroll
    for (int s = 0; s < 4; s++) {
      int row = rb + s;
      p.o_out[(size_t)b * 512 + row * 64 + lane] =
          __half2float(ah[row * S_H + lane]) + __half2float(al[row * S_H + lane]);
      p.o_out[(size_t)b * 512 + row * 64 + lane + 32] =
          __half2float(ah[row * S_H + lane + 32]) + __half2float(al[row * S_H + lane + 32]);
    }
  }

  // ---------------- cross attention + color ----------------
  float* qr = s_ao + ray * S_A;
  if (half_ == 0) {
    qr[lane] = p.query[(size_t)b * 64 + lane];
    qr[lane + 32] = p.query[(size_t)b * 64 + lane + 32];
  }

  float ca0 = 0.f, ca1 = 0.f;
  for (int h = 0; h < 4; h++) {
    __syncthreads();
    stage_w_h(p.cWk + h * 64, 256, (__half*)w0h, (__half*)w0l, tid);
    stage_w_h(p.cWv + h * 64, 256, (__half*)w1h, (__half*)w1l, tid);
    stage_w_h(p.cWq + h * 64, 256, (__half*)w3h, (__half*)w3l, tid);
    stage_w_h(p.cWo + h * 4096, 64, (__half*)w2h, (__half*)w2l, tid);
    __syncthreads();
    {
      float ck[2][4] = {}, cv[2][4] = {};
      gemm2_acc(uacth, uactl, w0h, w0l, w1h, w1l, lane, mt, nq, ck, cv);
      store_c(s_k, lane, mt, nq, ck, p.cbk + h * 64, 0, nullptr, nullptr);
      store_c(s_v, lane, mt, nq, cv, p.cbv + h * 64, 0, nullptr, nullptr);
    }
    __syncthreads();
    if (half_ == 0) {
      float cq0 = __ldg(p.cbq + h * 64 + lane);
      float cq1 = __ldg(p.cbq + h * 64 + lane + 32);
      #pragma unroll 8
      for (int k = 0; k < 64; k += 2) {
        int wi = k >> 1;
        float a0 = qr[k], a1 = qr[k + 1];
        float2 wv0 = h2f(w3h[lane * 36 + wi]);
        float2 wl0_ = h2f(w3l[lane * 36 + wi]);
        float2 wv1 = h2f(w3h[(lane + 32) * 36 + wi]);
        float2 wl1_ = h2f(w3l[(lane + 32) * 36 + wi]);
        cq0 = fmaf(a0, wv0.x + wl0_.x, cq0);
        cq0 = fmaf(a1, wv0.y + wl0_.y, cq0);
        cq1 = fmaf(a0, wv1.x + wl1_.x, cq1);
        cq1 = fmaf(a1, wv1.y + wl1_.y, cq1);
      }
      const float* kb = s_k + ray * 8 * S_A;
      const float* vb = s_v + ray * 8 * S_A;
      float e[8];
      #pragma unroll
      for (int k = 0; k < 8; k++) {
        float pk = cq0 * kb[k * S_A + lane] + cq1 * kb[k * S_A + lane + 32];
        #pragma unroll
        for (int o = 16; o > 0; o >>= 1) pk += __shfl_xor_sync(0xffffffffu, pk, o);
        e[k] = pk * 0.125f;
      }
      float mm = e[0];
      #pragma unroll
      for (int k = 1; k < 8; k++) mm = fmaxf(mm, e[k]);
      float prb[8], sum = 0.f;
      #pragma unroll
      for (int k = 0; k < 8; k++) { prb[k] = __expf(e[k] - mm); sum += prb[k]; }
      float inv = __fdividef(1.f, sum);
      float cx0 = 0.f, cx1 = 0.f;
      #pragma unroll
      for (int k = 0; k < 8; k++) {
        float pk = prb[k] * inv;
        cx0 = fmaf(pk, vb[k * S_A + lane], cx0);
        cx1 = fmaf(pk, vb[k * S_A + lane + 32], cx1);
      }
      my_p[lane] = cx0;
      my_p[lane + 32] = cx1;
      __syncwarp();
      if (h == 0) { ca0 = __ldg(p.cbo + lane); ca1 = __ldg(p.cbo + lane + 32); }
      #pragma unroll 8
      for (int k = 0; k < 64; k += 2) {
        int wi = k >> 1;
        float a0 = my_p[k], a1 = my_p[k + 1];
        float2 wv0 = h2f(w2h[lane * 36 + wi]);
        float2 wl0_ = h2f(w2l[lane * 36 + wi]);
        float2 wv1 = h2f(w2h[(lane + 32) * 36 + wi]);
        float2 wl1_ = h2f(w2l[(lane + 32) * 36 + wi]);
        ca0 = fmaf(a0, wv0.x + wl0_.x, ca0);
        ca0 = fmaf(a1, wv0.y + wl0_.y, ca0);
        ca1 = fmaf(a0, wv1.x + wl1_.x, ca1);
        ca1 = fmaf(a1, wv1.y + wl1_.y, ca1);
      }
    }
  }

  if (half_ == 0) {
    float r0 = fmaxf(ca0, 0.f), r1 = fmaxf(ca1, 0.f);
    #pragma unroll
    for (int t = 0; t < 3; t++) {
      float part = r0 * __ldg(p.Wc + lane * 3 + t) + r1 * __ldg(p.Wc + (lane + 32) * 3 + t);
      #pragma unroll
      for (int o = 16; o > 0; o >>= 1) part += __shfl_xor_sync(0xffffffffu, part, o);
      if (lane == 0) p.o_color[(size_t)b * 3 + t] = part + __ldg(p.bc + t);
    }
  }
}

extern "C" void kernel_launch(void* const* d_in, const int* in_sizes, int n_in,
                              void* d_out, int out_size) {
  Params p;
  p.query = (const float*)d_in[0];
  p.latent = (const float*)d_in[1];
  p.W1 = (const float*)d_in[2];
  p.b1 = (const float*)d_in[3];
  p.Wq = (const float*)d_in[4];
  p.bq = (const float*)d_in[5];
  p.Wk = (const float*)d_in[6];
  p.bk = (const float*)d_in[7];
  p.Wv = (const float*)d_in[8];
  p.bv = (const float*)d_in[9];
  p.Wo = (const float*)d_in[10];
  p.bo = (const float*)d_in[11];
  p.fW1 = (const float*)d_in[12];
  p.fb1 = (const float*)d_in[13];
  p.fW2 = (const float*)d_in[14];
  p.fb2 = (const float*)d_in[15];
  p.g1 = (const float*)d_in[16];
  p.be1 = (const float*)d_in[17];
  p.g2 = (const float*)d_in[18];
  p.be2 = (const float*)d_in[19];
  p.cWq = (const float*)d_in[20];
  p.cbq = (const float*)d_in[21];
  p.cWk = (const float*)d_in[22];
  p.cbk = (const float*)d_in[23];
  p.cWv = (const float*)d_in[24];
  p.cbv = (const float*)d_in[25];
  p.cWo = (const float*)d_in[26];
  p.cbo = (const float*)d_in[27];
  p.Wc = (const float*)d_in[28];
  p.bc = (const float*)d_in[29];
  p.Ws = (const float*)d_in[30];
  p.bs = (const float*)d_in[31];

  float* o = (float*)d_out;
  p.o_color = o;                                    // [B,1,3]
  p.o_sigma = o + (size_t)B_TOTAL * 3;              // [B,1]
  p.o_out = o + (size_t)B_TOTAL * 4;                // [B,8,64]
  p.o_attn = o + (size_t)B_TOTAL * 4 + (size_t)B_TOTAL * 512;  // [B,4,4,8,8]

  cudaFuncSetAttribute(rt_kernel, cudaFuncAttributeMaxDynamicSharedMemorySize,
                       SMEM_BYTES);
  rt_kernel<<<NBLOCKS, NTHREADS, SMEM_BYTES>>>(p);
}

// round 16
// speedup vs baseline: 1.6997x; 1.5402x over previous
#include <cuda_runtime.h>
#include <cuda_fp16.h>

typedef unsigned long long ull;
typedef unsigned int uint;

#define NTHREADS 512
#define RAYS 8
#define NBLOCKS 4096
#define B_TOTAL 32768
#define S_A 68      // fp32 tile stride (floats)
#define S_H 72      // half tile stride (halves); word stride 36

// smem offsets (floats); half tile = 64x72 halves = 2304 floats
#define OFF_Q    0
#define OFF_K    4352
#define OFF_V    8704
#define OFF_AO   13056
#define OFF_ACTH 17408
#define OFF_ACTL 19712
#define OFF_XH   22016
#define OFF_XL   24320
#define OFF_W0H  26624
#define OFF_W0L  28928
#define OFF_W1H  31232
#define OFF_W1L  33536
#define OFF_W2H  35840
#define OFF_W2L  38144
#define OFF_W3H  40448
#define OFF_W3L  42752
#define OFF_P    45056
#define SMEM_FLOATS (45056 + 512)   // 182272 B
#define SMEM_BYTES (SMEM_FLOATS * 4)

struct Params {
  const float *query, *latent, *W1, *b1;
  const float *Wq, *bq, *Wk, *bk, *Wv, *bv, *Wo, *bo;
  const float *fW1, *fb1, *fW2, *fb2, *g1, *be1, *g2, *be2;
  const float *cWq, *cbq, *cWk, *cbk, *cWv, *cbv, *cWo, *cbo;
  const float *Wc, *bc, *Ws, *bs;
  float *o_color, *o_sigma, *o_out, *o_attn;
};

// ---------------- helpers ----------------
__device__ __forceinline__ ull ffma2(ull a, ull b, ull c) {
  ull d;
  asm("fma.rn.f32x2 %0, %1, %2, %3;" : "=l"(d) : "l"(a), "l"(b), "l"(c));
  return d;
}
__device__ __forceinline__ ull pack2(float lo, float hi) {
  ull d;
  asm("mov.b64 %0, {%1, %2};" : "=l"(d) : "f"(lo), "f"(hi));
  return d;
}
__device__ __forceinline__ float2 unpack2(ull v) {
  float lo, hi;
  asm("mov.b64 {%0, %1}, %2;" : "=f"(lo), "=f"(hi) : "l"(v));
  return make_float2(lo, hi);
}
__device__ __forceinline__ uint hpackr(float a, float b, float& ra, float& rb) {
  __half ha = __float2half_rn(a), hb = __float2half_rn(b);
  ra = a - __half2float(ha);
  rb = b - __half2float(hb);
  __half2 p = __halves2half2(ha, hb);
  return *(uint*)&p;
}
__device__ __forceinline__ uint hpack(float a, float b) {
  __half2 p = __halves2half2(__float2half_rn(a), __float2half_rn(b));
  return *(uint*)&p;
}
__device__ __forceinline__ float2 h2f(uint u) {
  return __half22float2(*(__half2*)&u);
}
__device__ __forceinline__ void hsplit1(float x, __half& h, __half& l) {
  h = __float2half_rn(x);
  l = __float2half_rn(x - __half2float(h));
}

__device__ __forceinline__ void mma16(float c[4], uint a0, uint a1, uint a2, uint a3,
                                      uint b0, uint b1) {
  asm("mma.sync.aligned.m16n8k16.row.col.f32.f16.f16.f32 "
      "{%0,%1,%2,%3},{%4,%5,%6,%7},{%8,%9},{%0,%1,%2,%3};"
      : "+f"(c[0]), "+f"(c[1]), "+f"(c[2]), "+f"(c[3])
      : "r"(a0), "r"(a1), "r"(a2), "r"(a3), "r"(b0), "r"(b1));
}

struct AF { uint h[4], l[4]; };
__device__ __forceinline__ AF load_a(const uint* __restrict__ Ah,
                                     const uint* __restrict__ Al,
                                     int lane, int mt, int kk) {
  const int grp = lane >> 2, kq = lane & 3;
  const int base = (mt * 16 + grp) * 36 + kk * 8 + kq;
  AF f;
  f.h[0] = Ah[base];
  f.h[1] = Ah[base + 8 * 36];
  f.h[2] = Ah[base + 4];
  f.h[3] = Ah[base + 8 * 36 + 4];
  f.l[0] = Al[base];
  f.l[1] = Al[base + 8 * 36];
  f.l[2] = Al[base + 4];
  f.l[3] = Al[base + 8 * 36 + 4];
  return f;
}
__device__ __forceinline__ void mma3h(float c[4], const AF& a,
                                      uint wh0, uint wh1, uint wl0, uint wl1) {
  mma16(c, a.h[0], a.h[1], a.h[2], a.h[3], wh0, wh1);
  mma16(c, a.l[0], a.l[1], a.l[2], a.l[3], wh0, wh1);
  mma16(c, a.h[0], a.h[1], a.h[2], a.h[3], wl0, wl1);
}

// 16-warp m16n16 single gemm (stage0, FF1, FF2, out-proj)
__device__ __forceinline__ void gemm_acc(const uint* Ah, const uint* Al,
                                         const uint* Wh, const uint* Wl,
                                         int lane, int mt, int nq, float c[2][4]) {
  const int grp = lane >> 2, kq = lane & 3;
  #pragma unroll
  for (int kk = 0; kk < 4; kk++) {
    AF a = load_a(Ah, Al, lane, mt, kk);
    const int off = (nq * 16 + grp) * 36 + kk * 8 + kq;
    #pragma unroll
    for (int t = 0; t < 2; t++) {
      const int o = off + t * 8 * 36;
      mma3h(c[t], a, Wh[o], Wh[o + 4], Wl[o], Wl[o + 4]);
    }
  }
}
__device__ __forceinline__ void gemm2_acc(const uint* Ah, const uint* Al,
                                          const uint* W0h, const uint* W0l,
                                          const uint* W1h, const uint* W1l,
                                          int lane, int mt, int nq,
                                          float c0[2][4], float c1[2][4]) {
  const int grp = lane >> 2, kq = lane & 3;
  #pragma unroll
  for (int kk = 0; kk < 4; kk++) {
    AF a = load_a(Ah, Al, lane, mt, kk);
    const int off = (nq * 16 + grp) * 36 + kk * 8 + kq;
    #pragma unroll
    for (int t = 0; t < 2; t++) {
      const int o = off + t * 8 * 36;
      mma3h(c0[t], a, W0h[o], W0h[o + 4], W0l[o], W0l[o + 4]);
      mma3h(c1[t], a, W1h[o], W1h[o + 4], W1l[o], W1l[o + 4]);
    }
  }
}
// 16-warp fused QKV
__device__ __forceinline__ void gemm3_acc(const uint* Ah, const uint* Al,
                                          const uint* W0h, const uint* W0l,
                                          const uint* W1h, const uint* W1l,
                                          const uint* W2h, const uint* W2l,
                                          int lane, int mt, int nq,
                                          float c0[2][4], float c1[2][4],
                                          float c2[2][4]) {
  const int grp = lane >> 2, kq = lane & 3;
  #pragma unroll
  for (int kk = 0; kk < 4; kk++) {
    AF a = load_a(Ah, Al, lane, mt, kk);
    const int off = (nq * 16 + grp) * 36 + kk * 8 + kq;
    #pragma unroll
    for (int t = 0; t < 2; t++) {
      const int o = off + t * 8 * 36;
      mma3h(c0[t], a, W0h[o], W0h[o + 4], W0l[o], W0l[o + 4]);
      mma3h(c1[t], a, W1h[o], W1h[o + 4], W1l[o], W1l[o + 4]);
      mma3h(c2[t], a, W2h[o], W2h[o + 4], W2l[o], W2l[o + 4]);
    }
  }
}

__device__ __forceinline__ void store_c(float* D, int lane, int mt, int nq,
                                        const float c[2][4], const float* bias,
                                        int do_relu, const uint* rh, const uint* rl) {
  const int grp = lane >> 2, kq = lane & 3;
  const int r = mt * 16 + grp;
  #pragma unroll
  for (int t = 0; t < 2; t++) {
    int col = nq * 16 + t * 8 + 2 * kq;
    float b0 = __ldg(bias + col), b1 = __ldg(bias + col + 1);
    float v0 = c[t][0] + b0, v1 = c[t][1] + b1;
    float v2 = c[t][2] + b0, v3 = c[t][3] + b1;
    if (rh) {
      int w0 = r * 36 + (col >> 1), w1 = (r + 8) * 36 + (col >> 1);
      float2 fh0 = h2f(rh[w0]), fl0 = h2f(rl[w0]);
      float2 fh1 = h2f(rh[w1]), fl1 = h2f(rl[w1]);
      v0 += fh0.x + fl0.x; v1 += fh0.y + fl0.y;
      v2 += fh1.x + fl1.x; v3 += fh1.y + fl1.y;
    }
    if (do_relu) {
      v0 = fmaxf(v0, 0.f); v1 = fmaxf(v1, 0.f);
      v2 = fmaxf(v2, 0.f); v3 = fmaxf(v3, 0.f);
    }
    *(float2*)(D + r * S_A + col) = make_float2(v0, v1);
    *(float2*)(D + (r + 8) * S_A + col) = make_float2(v2, v3);
  }
}

__device__ __forceinline__ void store_c_h(uint* Dh, uint* Dl, int lane, int mt, int nq,
                                          const float c[2][4], const float* bias,
                                          int do_relu) {
  const int grp = lane >> 2, kq = lane & 3;
  const int r = mt * 16 + grp;
  #pragma unroll
  for (int t = 0; t < 2; t++) {
    int col = nq * 16 + t * 8 + 2 * kq;
    float b0 = __ldg(bias + col), b1 = __ldg(bias + col + 1);
    float v0 = c[t][0] + b0, v1 = c[t][1] + b1;
    float v2 = c[t][2] + b0, v3 = c[t][3] + b1;
    if (do_relu) {
      v0 = fmaxf(v0, 0.f); v1 = fmaxf(v1, 0.f);
      v2 = fmaxf(v2, 0.f); v3 = fmaxf(v3, 0.f);
    }
    float ra, rb;
    uint h01 = hpackr(v0, v1, ra, rb);
    uint l01 = hpack(ra, rb);
    Dh[r * 36 + (col >> 1)] = h01;
    Dl[r * 36 + (col >> 1)] = l01;
    uint h23 = hpackr(v2, v3, ra, rb);
    uint l23 = hpack(ra, rb);
    Dh[(r + 8) * 36 + (col >> 1)] = h23;
    Dl[(r + 8) * 36 + (col >> 1)] = l23;
  }
}

// stage 64x64 fp32 weight [k][n] -> transposed [n][k] half hi/lo tiles
__device__ __forceinline__ void stage_w_h(const float* __restrict__ src, int stride,
                                          __half* __restrict__ dh,
                                          __half* __restrict__ dl, int tid) {
  #pragma unroll
  for (int it = 0; it < 2; it++) {
    int i = tid + it * NTHREADS;
    int n = i & 63, k4 = (i >> 6) << 2;
    float v0 = src[(k4 + 0) * stride + n];
    float v1 = src[(k4 + 1) * stride + n];
    float v2 = src[(k4 + 2) * stride + n];
    float v3 = src[(k4 + 3) * stride + n];
    float r0, r1, r2, r3;
    uint2 hw, lw;
    hw.x = hpackr(v0, v1, r0, r1);
    hw.y = hpackr(v2, v3, r2, r3);
    lw.x = hpack(r0, r1);
    lw.y = hpack(r2, r3);
    *(uint2*)(dh + n * S_H + k4) = hw;
    *(uint2*)(dl + n * S_H + k4) = lw;
  }
}

__device__ __forceinline__ void ln4(const float* s1, const __half* s2h,
                                    const __half* s2l, const float* g,
                                    const float* be, int lane,
                                    __half* dh, __half* dl) {
  float gg0 = __ldg(g + lane), gg1 = __ldg(g + lane + 32);
  float bb0 = __ldg(be + lane), bb1 = __ldg(be + lane + 32);
  #pragma unroll
  for (int s = 0; s < 4; s++) {
    float x0 = s1[s * S_A + lane];
    float x1 = s1[s * S_A + lane + 32];
    if (s2h) {
      x0 += __half2float(s2h[s * S_H + lane]) + __half2float(s2l[s * S_H + lane]);
      x1 += __half2float(s2h[s * S_H + lane + 32]) + __half2float(s2l[s * S_H + lane + 32]);
    }
    float sum = x0 + x1;
    #pragma unroll
    for (int o = 16; o > 0; o >>= 1) sum += __shfl_xor_sync(0xffffffffu, sum, o);
    float mean = sum * 0.015625f;
    float d0 = x0 - mean, d1 = x1 - mean;
    float vs = d0 * d0 + d1 * d1;
    #pragma unroll
    for (int o = 16; o > 0; o >>= 1) vs += __shfl_xor_sync(0xffffffffu, vs, o);
    float rstd = rsqrtf(vs * 0.015625f + 1e-5f);
    float y0 = d0 * rstd * gg0 + bb0;
    float y1 = d1 * rstd * gg1 + bb1;
    __half h, l;
    hsplit1(y0, h, l);
    dh[s * S_H + lane] = h; dl[s * S_H + lane] = l;
    hsplit1(y1, h, l);
    dh[s * S_H + lane + 32] = h; dl[s * S_H + lane + 32] = l;
  }
}

#define STAGE_LAT(DH, DL, KC)                                                  \
  do {                                                                         \
    _Pragma("unroll")                                                          \
    for (int it_ = 0; it_ < 2; it_++) {                                        \
      int i_ = tid + it_ * NTHREADS;                                           \
      int row_ = i_ >> 4, j_ = (i_ & 15) * 4;                                  \
      float4 v_ = *(const float4*)(p.latent + (size_t)(bbase + (row_ >> 3)) * 4096 + \
                                   (row_ & 7) * 512 + (KC) * 64 + j_);         \
      float r0_, r1_, r2_, r3_;                                                \
      uint2 hw_, lw_;                                                          \
      hw_.x = hpackr(v_.x, v_.y, r0_, r1_);                                    \
      hw_.y = hpackr(v_.z, v_.w, r2_, r3_);                                    \
      lw_.x = hpack(r0_, r1_);                                                 \
      lw_.y = hpack(r2_, r3_);                                                 \
      *(uint2*)((DH) + row_ * S_H + j_) = hw_;                                 \
      *(uint2*)((DL) + row_ * S_H + j_) = lw_;                                 \
    }                                                                          \
  } while (0)

__global__ void __launch_bounds__(NTHREADS, 1) rt_kernel(Params p) {
  extern __shared__ float sm[];
  const int tid = threadIdx.x;
  const int warp = tid >> 5, lane = tid & 31;
  const int mt = warp & 3, nq = warp >> 2;
  const int ray = warp & 7, half_ = warp >> 3, rb = half_ * 4;
  const int bbase = blockIdx.x * RAYS;
  const int b = bbase + ray;

  float* s_q = sm + OFF_Q;
  float* s_k = sm + OFF_K;
  float* s_v = sm + OFF_V;
  float* s_ao = sm + OFF_AO;
  __half* acth = (__half*)(sm + OFF_ACTH);
  __half* actl = (__half*)(sm + OFF_ACTL);
  __half* xh = (__half*)(sm + OFF_XH);
  __half* xl = (__half*)(sm + OFF_XL);
  uint* uacth = (uint*)acth;
  uint* uactl = (uint*)actl;
  uint* uxh = (uint*)xh;
  uint* uxl = (uint*)xl;
  uint* w0h = (uint*)(sm + OFF_W0H); uint* w0l = (uint*)(sm + OFF_W0L);
  uint* w1h = (uint*)(sm + OFF_W1H); uint* w1l = (uint*)(sm + OFF_W1L);
  uint* w2h = (uint*)(sm + OFF_W2H); uint* w2l = (uint*)(sm + OFF_W2L);
  uint* w3h = (uint*)(sm + OFF_W3H); uint* w3l = (uint*)(sm + OFF_W3L);
  float* my_p = sm + OFF_P + ray * 64;

  // ---------------- stage 0: act = relu(latent @ W1 + b1), K=512 ----------------
  {
    stage_w_h(p.W1, 64, (__half*)w0h, (__half*)w0l, tid);
    STAGE_LAT(acth, actl, 0);
    __syncthreads();
    float c[2][4] = {};
    for (int kc = 0; kc < 8; kc++) {
      const uint* lbh = (kc & 1) ? uxh : uacth;
      const uint* lbl = (kc & 1) ? uxl : uactl;
      const uint* wbh = (kc & 1) ? w1h : w0h;
      const uint* wbl = (kc & 1) ? w1l : w0l;
      if (kc < 7) {
        stage_w_h(p.W1 + (kc + 1) * 4096, 64,
                  (kc & 1) ? (__half*)w0h : (__half*)w1h,
                  (kc & 1) ? (__half*)w0l : (__half*)w1l, tid);
        if (kc & 1) STAGE_LAT(acth, actl, kc + 1);
        else        STAGE_LAT(xh, xl, kc + 1);
      }
      gemm_acc(lbh, lbl, wbh, wbl, lane, mt, nq, c);
      __syncthreads();
    }
    store_c_h(uacth, uactl, lane, mt, nq, c, p.b1, 1);
  }
  __syncthreads();
  // stage layer0 head0 QKV (serial)
  stage_w_h(p.Wq, 256, (__half*)w0h, (__half*)w0l, tid);
  stage_w_h(p.Wk, 256, (__half*)w1h, (__half*)w1l, tid);
  stage_w_h(p.Wv, 256, (__half*)w2h, (__half*)w2l, tid);
  __syncthreads();

  // ---------------- 4 transformer layers ----------------
  for (int l = 0; l < 4; l++) {
    if (l > 0) {
      stage_w_h(p.Wq + l * 16384, 256, (__half*)w0h, (__half*)w0l, tid);
      stage_w_h(p.Wk + l * 16384, 256, (__half*)w1h, (__half*)w1l, tid);
      stage_w_h(p.Wv + l * 16384, 256, (__half*)w2h, (__half*)w2l, tid);
      __syncthreads();
    }

    float co[2][4] = {};   // out-proj accumulator across heads
    for (int h = 0; h < 4; h++) {
      // fused QKV (one A pass, pre-split everything)
      {
        float cq[2][4] = {}, ck[2][4] = {}, cv[2][4] = {};
        gemm3_acc(uacth, uactl, w0h, w0l, w1h, w1l, w2h, w2l,
                  lane, mt, nq, cq, ck, cv);
        store_c(s_q, lane, mt, nq, cq, p.bq + l * 256 + h * 64, 0, nullptr, nullptr);
        store_c(s_k, lane, mt, nq, ck, p.bk + l * 256 + h * 64, 0, nullptr, nullptr);
        store_c(s_v, lane, mt, nq, cv, p.bv + l * 256 + h * 64, 0, nullptr, nullptr);
      }
      __syncthreads();   // (A) QKV visible

      // stage next weights; LDG latency overlapped by attention below
      stage_w_h(p.Wo + l * 16384 + h * 4096, 64, (__half*)w3h, (__half*)w3l, tid);
      if (h < 3) {
        stage_w_h(p.Wq + l * 16384 + (h + 1) * 64, 256, (__half*)w0h, (__half*)w0l, tid);
        stage_w_h(p.Wk + l * 16384 + (h + 1) * 64, 256, (__half*)w1h, (__half*)w1l, tid);
        stage_w_h(p.Wv + l * 16384 + (h + 1) * 64, 256, (__half*)w2h, (__half*)w2l, tid);
      } else {
        stage_w_h(p.fW1 + l * 4096, 64, (__half*)w0h, (__half*)w0l, tid);
        stage_w_h(p.fW2 + l * 4096, 64, (__half*)w1h, (__half*)w1l, tid);
      }

      // ---- attention (scalar fp32): warp pair per ray, 4 q-rows each ----
      {
        const float* qb = s_q + ray * 8 * S_A;
        const float* kb = s_k + ray * 8 * S_A;
        const float* vb = s_v + ray * 8 * S_A;
        int idx = half_ * 32 + lane;
        int qi = idx >> 3, ki = idx & 7;
        const float* qr = qb + qi * S_A;
        const float* kr = kb + ki * S_A;
        ull acc = pack2(0.f, 0.f);
        #pragma unroll
        for (int j = 0; j < 64; j += 4) {
          ulonglong2 qq = *(const ulonglong2*)(qr + j);
          ulonglong2 kk2 = *(const ulonglong2*)(kr + j);
          acc = ffma2(qq.x, kk2.x, acc);
          acc = ffma2(qq.y, kk2.y, acc);
        }
        float2 t = unpack2(acc);
        float sc = (t.x + t.y) * 0.125f;
        float m = sc;
        m = fmaxf(m, __shfl_xor_sync(0xffffffffu, m, 1));
        m = fmaxf(m, __shfl_xor_sync(0xffffffffu, m, 2));
        m = fmaxf(m, __shfl_xor_sync(0xffffffffu, m, 4));
        float e = __expf(sc - m);
        float se = e;
        se += __shfl_xor_sync(0xffffffffu, se, 1);
        se += __shfl_xor_sync(0xffffffffu, se, 2);
        se += __shfl_xor_sync(0xffffffffu, se, 4);
        float pr = __fdividef(e, se);
        my_p[idx] = pr;
        p.o_attn[(size_t)b * 1024 + (size_t)l * 256 + h * 64 + idx] = pr;
        __syncwarp();
        float cx[8];
        #pragma unroll
        for (int i = 0; i < 8; i++) cx[i] = 0.f;
        #pragma unroll
        for (int kj = 0; kj < 8; kj++) {
          float vx = vb[kj * S_A + lane];
          float vy = vb[kj * S_A + lane + 32];
          #pragma unroll
          for (int ql = 0; ql < 4; ql++) {
            float pk = my_p[(rb + ql) * 8 + kj];
            cx[2 * ql] = fmaf(pk, vx, cx[2 * ql]);
            cx[2 * ql + 1] = fmaf(pk, vy, cx[2 * ql + 1]);
          }
        }
        #pragma unroll
        for (int ql = 0; ql < 4; ql++) {
          int row = ray * 8 + rb + ql;
          __half hh, hl;
          hsplit1(cx[2 * ql], hh, hl);
          xh[row * S_H + lane] = hh; xl[row * S_H + lane] = hl;
          hsplit1(cx[2 * ql + 1], hh, hl);
          xh[row * S_H + lane + 32] = hh; xl[row * S_H + lane + 32] = hl;
        }
      }
      __syncthreads();   // (B) ctx + staged weights visible

      // out-proj: co += ctx @ Wo_h  (x readers finish before sync-A of h+1)
      gemm_acc(uxh, uxl, w3h, w3l, lane, mt, nq, co);
    }  // heads

    store_c(s_ao, lane, mt, nq, co, p.bo + l * 64, 0, nullptr, nullptr);
    __syncthreads();
    // LN1: act = LN(ao + act)
    ln4(s_ao + (ray * 8 + rb) * S_A,
        acth + (ray * 8 + rb) * S_H, actl + (ray * 8 + rb) * S_H,
        p.g1 + l * 64, p.be1 + l * 64, lane,
        acth + (ray * 8 + rb) * S_H, actl + (ray * 8 + rb) * S_H);
    __syncthreads();
    // FF1 (fW1 in w0 pair, staged during h==3)
    {
      float c[2][4] = {};
      gemm_acc(uacth, uactl, w0h, w0l, lane, mt, nq, c);
      store_c_h(uxh, uxl, lane, mt, nq, c, p.fb1 + l * 64, 1);
    }
    __syncthreads();
    // FF2 + residual(act halves) -> ao fp32
    {
      float c[2][4] = {};
      gemm_acc(uxh, uxl, w1h, w1l, lane, mt, nq, c);
      store_c(s_ao, lane, mt, nq, c, p.fb2 + l * 64, 0, uacth, uactl);
    }
    __syncthreads();
    // LN2: act = LN(ao)
    ln4(s_ao + (ray * 8 + rb) * S_A, nullptr, nullptr,
        p.g2 + l * 64, p.be2 + l * 64, lane,
        acth + (ray * 8 + rb) * S_H, actl + (ray * 8 + rb) * S_H);
    __syncthreads();
  }  // layers

  // ---------------- sigma & out ----------------
  {
    const __half* ah = acth + ray * 8 * S_H;
    const __half* al = actl + ray * 8 * S_H;
    if (half_ == 0) {
      float m0 = -1e30f, m1 = -1e30f;
      #pragma unroll
      for (int s = 0; s < 8; s++) {
        m0 = fmaxf(m0, __half2float(ah[s * S_H + lane]) + __half2float(al[s * S_H + lane]));
        m1 = fmaxf(m1, __half2float(ah[s * S_H + lane + 32]) + __half2float(al[s * S_H + lane + 32]));
      }
      float part = m0 * __ldg(p.Ws + lane) + m1 * __ldg(p.Ws + lane + 32);
      #pragma unroll
      for (int o = 16; o > 0; o >>= 1) part += __shfl_xor_sync(0xffffffffu, part, o);
      if (lane == 0) p.o_sigma[b] = part + __ldg(p.bs);
    }
    #pragma unroll
    for (int s = 0; s < 4; s++) {
      int row = rb + s;
      p.o_out[(size_t)b * 512 + row * 64 + lane] =
          __half2float(ah[row * S_H + lane]) + __half2float(al[row * S_H + lane]);
      p.o_out[(size_t)b * 512 + row * 64 + lane + 32] =
          __half2float(ah[row * S_H + lane + 32]) + __half2float(al[row * S_H + lane + 32]);
    }
  }

  // ---------------- cross attention + color ----------------
  float* qr = s_ao + ray * S_A;  // query row (fp32; ao free here)
  if (half_ == 0) {
    qr[lane] = p.query[(size_t)b * 64 + lane];
    qr[lane + 32] = p.query[(size_t)b * 64 + lane + 32];
  }

  float ca0 = 0.f, ca1 = 0.f;
  for (int h = 0; h < 4; h++) {
    __syncthreads();
    stage_w_h(p.cWk + h * 64, 256, (__half*)w0h, (__half*)w0l, tid);
    stage_w_h(p.cWv + h * 64, 256, (__half*)w1h, (__half*)w1l, tid);
    stage_w_h(p.cWq + h * 64, 256, (__half*)w3h, (__half*)w3l, tid);
    stage_w_h(p.cWo + h * 4096, 64, (__half*)w2h, (__half*)w2l, tid);
    __syncthreads();
    {
      float ck[2][4] = {}, cv[2][4] = {};
      gemm2_acc(uacth, uactl, w0h, w0l, w1h, w1l, lane, mt, nq, ck, cv);
      store_c(s_k, lane, mt, nq, ck, p.cbk + h * 64, 0, nullptr, nullptr);
      store_c(s_v, lane, mt, nq, cv, p.cbv + h * 64, 0, nullptr, nullptr);
    }
    __syncthreads();
    if (half_ == 0) {
      float cq0 = __ldg(p.cbq + h * 64 + lane);
      float cq1 = __ldg(p.cbq + h * 64 + lane + 32);
      #pragma unroll 8
      for (int k = 0; k < 64; k += 2) {
        int wi = k >> 1;
        float a0 = qr[k], a1 = qr[k + 1];
        float2 wv0 = h2f(w3h[lane * 36 + wi]);
        float2 wl0_ = h2f(w3l[lane * 36 + wi]);
        float2 wv1 = h2f(w3h[(lane + 32) * 36 + wi]);
        float2 wl1_ = h2f(w3l[(lane + 32) * 36 + wi]);
        cq0 = fmaf(a0, wv0.x + wl0_.x, cq0);
        cq0 = fmaf(a1, wv0.y + wl0_.y, cq0);
        cq1 = fmaf(a0, wv1.x + wl1_.x, cq1);
        cq1 = fmaf(a1, wv1.y + wl1_.y, cq1);
      }
      const float* kb = s_k + ray * 8 * S_A;
      const float* vb = s_v + ray * 8 * S_A;
      float e[8];
      #pragma unroll
      for (int k = 0; k < 8; k++) {
        float pk = cq0 * kb[k * S_A + lane] + cq1 * kb[k * S_A + lane + 32];
        #pragma unroll
        for (int o = 16; o > 0; o >>= 1) pk += __shfl_xor_sync(0xffffffffu, pk, o);
        e[k] = pk * 0.125f;
      }
      float mm = e[0];
      #pragma unroll
      for (int k = 1; k < 8; k++) mm = fmaxf(mm, e[k]);
      float prb[8], sum = 0.f;
      #pragma unroll
      for (int k = 0; k < 8; k++) { prb[k] = __expf(e[k] - mm); sum += prb[k]; }
      float inv = __fdividef(1.f, sum);
      float cx0 = 0.f, cx1 = 0.f;
      #pragma unroll
      for (int k = 0; k < 8; k++) {
        float pk = prb[k] * inv;
        cx0 = fmaf(pk, vb[k * S_A + lane], cx0);
        cx1 = fmaf(pk, vb[k * S_A + lane + 32], cx1);
      }
      my_p[lane] = cx0;
      my_p[lane + 32] = cx1;
      __syncwarp();
      if (h == 0) { ca0 = __ldg(p.cbo + lane); ca1 = __ldg(p.cbo + lane + 32); }
      #pragma unroll 8
      for (int k = 0; k < 64; k += 2) {
        int wi = k >> 1;
        float a0 = my_p[k], a1 = my_p[k + 1];
        float2 wv0 = h2f(w2h[lane * 36 + wi]);
        float2 wl0_ = h2f(w2l[lane * 36 + wi]);
        float2 wv1 = h2f(w2h[(lane + 32) * 36 + wi]);
        float2 wl1_ = h2f(w2l[(lane + 32) * 36 + wi]);
        ca0 = fmaf(a0, wv0.x + wl0_.x, ca0);
        ca0 = fmaf(a1, wv0.y + wl0_.y, ca0);
        ca1 = fmaf(a0, wv1.x + wl1_.x, ca1);
        ca1 = fmaf(a1, wv1.y + wl1_.y, ca1);
      }
    }
  }

  if (half_ == 0) {
    float r0 = fmaxf(ca0, 0.f), r1 = fmaxf(ca1, 0.f);
    #pragma unroll
    for (int t = 0; t < 3; t++) {
      float part = r0 * __ldg(p.Wc + lane * 3 + t) + r1 * __ldg(p.Wc + (lane + 32) * 3 + t);
      #pragma unroll
      for (int o = 16; o > 0; o >>= 1) part += __shfl_xor_sync(0xffffffffu, part, o);
      if (lane == 0) p.o_color[(size_t)b * 3 + t] = part + __ldg(p.bc + t);
    }
  }
}

extern "C" void kernel_launch(void* const* d_in, const int* in_sizes, int n_in,
                              void* d_out, int out_size) {
  Params p;
  p.query = (const float*)d_in[0];
  p.latent = (const float*)d_in[1];
  p.W1 = (const float*)d_in[2];
  p.b1 = (const float*)d_in[3];
  p.Wq = (const float*)d_in[4];
  p.bq = (const float*)d_in[5];
  p.Wk = (const float*)d_in[6];
  p.bk = (const float*)d_in[7];
  p.Wv = (const float*)d_in[8];
  p.bv = (const float*)d_in[9];
  p.Wo = (const float*)d_in[10];
  p.bo = (const float*)d_in[11];
  p.fW1 = (const float*)d_in[12];
  p.fb1 = (const float*)d_in[13];
  p.fW2 = (const float*)d_in[14];
  p.fb2 = (const float*)d_in[15];
  p.g1 = (const float*)d_in[16];
  p.be1 = (const float*)d_in[17];
  p.g2 = (const float*)d_in[18];
  p.be2 = (const float*)d_in[19];
  p.cWq = (const float*)d_in[20];
  p.cbq = (const float*)d_in[21];
  p.cWk = (const float*)d_in[22];
  p.cbk = (const float*)d_in[23];
  p.cWv = (const float*)d_in[24];
  p.cbv = (const float*)d_in[25];
  p.cWo = (const float*)d_in[26];
  p.cbo = (const float*)d_in[27];
  p.Wc = (const float*)d_in[28];
  p.bc = (const float*)d_in[29];
  p.Ws = (const float*)d_in[30];
  p.bs = (const float*)d_in[31];

  float* o = (float*)d_out;
  p.o_color = o;                                    // [B,1,3]
  p.o_sigma = o + (size_t)B_TOTAL * 3;              // [B,1]
  p.o_out = o + (size_t)B_TOTAL * 4;                // [B,8,64]
  p.o_attn = o + (size_t)B_TOTAL * 4 + (size_t)B_TOTAL * 512;  // [B,4,4,8,8]

  cudaFuncSetAttribute(rt_kernel, cudaFuncAttributeMaxDynamicSharedMemorySize,
                       SMEM_BYTES);
  rt_kernel<<<NBLOCKS, NTHREADS, SMEM_BYTES>>>(p);
}